// round 9
// baseline (speedup 1.0000x reference)
#include <cuda_runtime.h>
#include <math.h>

// ---------------------------------------------------------------------------
// Problem constants: x[16,256,64,64], Wqkv[384,256], Wout[256,128], bout[256]
// HEADS=4, DIM_HEAD=32, N=4096
// ---------------------------------------------------------------------------
#define B_   16
#define C_   256
#define N_   4096
#define HEADS_ 4
#define DH_  32
#define INNER_ 128   // HEADS*DH
#define EPS_ 1e-5f

using u64 = unsigned long long;

// packed f32x2 helpers (Blackwell FFMA2 path)
__device__ __forceinline__ u64 pack2(float lo, float hi) {
    u64 r; asm("mov.b64 %0, {%1, %2};" : "=l"(r) : "f"(lo), "f"(hi)); return r;
}
__device__ __forceinline__ void fma2(u64 &d, u64 a, u64 b) {
    asm("fma.rn.f32x2 %0, %1, %2, %0;" : "+l"(d) : "l"(a), "l"(b));
}
__device__ __forceinline__ float2 unpack2(u64 v) {
    float2 f; asm("mov.b64 {%0, %1}, %2;" : "=f"(f.x), "=f"(f.y) : "l"(v)); return f;
}

// ---------------------------------------------------------------------------
// Scratch (device globals — no allocation allowed)
// ---------------------------------------------------------------------------
__device__ float g_qkv[B_ * 384 * N_];        // 96 MB: [b][r=0..383][n]
__device__ float g_mu[B_ * N_];
__device__ float g_rstd[B_ * N_];
__device__ float g_kmax[B_ * INNER_];         // per (b, h*32+d)
__device__ float g_kz[B_ * INNER_];
__device__ float g_ctx[B_ * HEADS_ * DH_ * DH_];   // [b][h][d][e]
__device__ float g_WqkvT[C_ * 384];           // [k][r]
__device__ float g_WoutT[INNER_ * C_];        // [k][c]

// ---------------------------------------------------------------------------
// K0: transpose weights (tiny, per-launch, deterministic)
// ---------------------------------------------------------------------------
__global__ void transpose_kernel(const float* __restrict__ Wqkv,
                                 const float* __restrict__ Wout) {
    int idx = blockIdx.x * 256 + threadIdx.x;
    if (idx < 384 * 256) {
        int r = idx / 256, k = idx % 256;
        g_WqkvT[k * 384 + r] = Wqkv[idx];
    }
    if (idx < 256 * 128) {
        int c = idx / 128, k = idx % 128;
        g_WoutT[k * 256 + c] = Wout[idx];
    }
}

// ---------------------------------------------------------------------------
// K1: per-pixel LayerNorm stats over channels (mu, rstd) — LN folded into GEMM
// grid(64, 16), 256 threads; block handles 64 consecutive pixels of batch b
// ---------------------------------------------------------------------------
__global__ void stats_kernel(const float* __restrict__ x,
                             float* __restrict__ mu, float* __restrict__ rstd) {
    __shared__ float ssum[4][64];
    __shared__ float ssq[4][64];
    int t = threadIdx.x;
    int p = t & 63, cg = t >> 6;
    int b = blockIdx.y;
    int n0 = blockIdx.x * 64;
    const float* xb = x + (size_t)b * C_ * N_ + n0 + p;
    float s = 0.f, sq = 0.f;
    #pragma unroll 8
    for (int c = cg * 64; c < cg * 64 + 64; c++) {
        float v = xb[(size_t)c * N_];
        s += v; sq += v * v;
    }
    ssum[cg][p] = s; ssq[cg][p] = sq;
    __syncthreads();
    if (t < 64) {
        float S = ssum[0][t] + ssum[1][t] + ssum[2][t] + ssum[3][t];
        float Q = ssq[0][t] + ssq[1][t] + ssq[2][t] + ssq[3][t];
        float m = S * (1.f / 256.f);
        float var = Q * (1.f / 256.f) - m * m;
        int idx = b * N_ + n0 + t;
        mu[idx] = m;
        rstd[idx] = rsqrtf(var + EPS_);
    }
}

// ---------------------------------------------------------------------------
// K2: qkv = Wqkv @ LN(x), f32x2 register-tiled GEMM.
// grid(64, 3, 16): x = 64-pixel tile, y = 128-row slab (q/k/v), z = batch.
// 256 threads: cg=t&15 -> 8 rows (4 f32x2 pairs), pg=t>>4 -> 4 pixels.
// ---------------------------------------------------------------------------
__global__ void qkv_kernel(const float* __restrict__ x) {
    __shared__ __align__(16) float Ws[32 * 132];  // [k][r pad 132]
    __shared__ __align__(16) float Bs[32 * 68];   // [k][p pad 68]

    const int t  = threadIdx.x;
    const int b  = blockIdx.z;
    const int mz = blockIdx.y;
    const int n0 = blockIdx.x * 64;
    const int m0 = mz * 128;

    const int cg = t & 15, pg = t >> 4;
    const int c0 = cg * 8, p0 = pg * 4;

    // loader coords
    const int pB = t & 63, kB = t >> 6;           // B tile: 4 k-rows, 8 passes
    const int rW = t & 127, kW0 = t >> 7;         // W tile: 2 k-rows, 16 passes
    const float mun = g_mu[b * N_ + n0 + pB];
    const float rsn = g_rstd[b * N_ + n0 + pB];

    u64 acc[4][4];
    #pragma unroll
    for (int i = 0; i < 4; i++)
        #pragma unroll
        for (int j = 0; j < 4; j++) acc[i][j] = 0ull;

    const float* xb = x + (size_t)b * C_ * N_ + n0;

    for (int kc = 0; kc < 256; kc += 32) {
        // stage B tile (normalized x) — coalesced global, conflict-free STS
        #pragma unroll
        for (int j = 0; j < 8; j++) {
            int k = kB + 4 * j;
            float v = xb[(size_t)(kc + k) * N_ + pB];
            Bs[k * 68 + pB] = (v - mun) * rsn;
        }
        // stage W tile from WqkvT (coalesced, conflict-free)
        #pragma unroll
        for (int j = 0; j < 16; j++) {
            int k = kW0 + 2 * j;
            Ws[k * 132 + rW] = g_WqkvT[(kc + k) * 384 + m0 + rW];
        }
        __syncthreads();

        #pragma unroll 8
        for (int k = 0; k < 32; k++) {
            const float4 bv = *reinterpret_cast<const float4*>(&Bs[k * 68 + p0]);
            u64 b2[4] = { pack2(bv.x, bv.x), pack2(bv.y, bv.y),
                          pack2(bv.z, bv.z), pack2(bv.w, bv.w) };
            const ulonglong2 w01 = *reinterpret_cast<const ulonglong2*>(&Ws[k * 132 + c0]);
            const ulonglong2 w23 = *reinterpret_cast<const ulonglong2*>(&Ws[k * 132 + c0 + 4]);
            u64 w[4] = { w01.x, w01.y, w23.x, w23.y };
            #pragma unroll
            for (int i = 0; i < 4; i++)
                #pragma unroll
                for (int j = 0; j < 4; j++)
                    fma2(acc[i][j], w[i], b2[j]);
        }
        __syncthreads();
    }

    float* outp = g_qkv + ((size_t)b * 384 + m0 + c0) * N_ + n0 + p0;
    #pragma unroll
    for (int i = 0; i < 4; i++) {
        float2 f0 = unpack2(acc[i][0]), f1 = unpack2(acc[i][1]);
        float2 f2 = unpack2(acc[i][2]), f3 = unpack2(acc[i][3]);
        float4 lo = make_float4(f0.x, f1.x, f2.x, f3.x);
        float4 hi = make_float4(f0.y, f1.y, f2.y, f3.y);
        *reinterpret_cast<float4*>(outp + (size_t)(2 * i) * N_)     = lo;
        *reinterpret_cast<float4*>(outp + (size_t)(2 * i + 1) * N_) = hi;
    }
}

// ---------------------------------------------------------------------------
// K3: k-softmax row stats over N for each (b, h*32+d). grid(128,16), 256 thr.
// ---------------------------------------------------------------------------
__global__ void kstats_kernel() {
    __shared__ float red[256];
    int t = threadIdx.x;
    int row = blockIdx.x;   // 0..127
    int b = blockIdx.y;
    const float* kp = g_qkv + ((size_t)b * 384 + 128 + row) * N_;
    float m = -1e30f;
    #pragma unroll 4
    for (int i = t; i < N_; i += 256) m = fmaxf(m, kp[i]);
    red[t] = m; __syncthreads();
    for (int s = 128; s > 0; s >>= 1) {
        if (t < s) red[t] = fmaxf(red[t], red[t + s]);
        __syncthreads();
    }
    m = red[0];
    __syncthreads();
    float z = 0.f;
    #pragma unroll 4
    for (int i = t; i < N_; i += 256) z += expf(kp[i] - m);
    red[t] = z; __syncthreads();
    for (int s = 128; s > 0; s >>= 1) {
        if (t < s) red[t] += red[t + s];
        __syncthreads();
    }
    if (t == 0) {
        int o = b * INNER_ + row;
        g_kmax[o] = m;
        g_kz[o] = red[0];
    }
}

// ---------------------------------------------------------------------------
// K4: ctx[b,h,d,e] = sum_n softmax_N(k)[n,d] * v[n,e] / N. grid(4,16), 1024 thr.
// ---------------------------------------------------------------------------
__global__ void ctx_kernel() {
    __shared__ __align__(16) float ws[32 * 132];
    __shared__ __align__(16) float vs[32 * 132];
    int t = threadIdx.x;
    int h = blockIdx.x, b = blockIdx.y;
    int d = t >> 5, e = t & 31;
    int dl = t >> 5, f4i = t & 31;   // loader coords
    const float* kbase = g_qkv + ((size_t)b * 384 + 128 + h * 32 + dl) * N_;
    const float* vbase = g_qkv + ((size_t)b * 384 + 256 + h * 32 + dl) * N_;
    float mrow = g_kmax[b * INNER_ + h * 32 + dl];
    float izrow = 1.f / g_kz[b * INNER_ + h * 32 + dl];
    float acc = 0.f;
    for (int nt = 0; nt < N_; nt += 128) {
        float4 kv = *reinterpret_cast<const float4*>(kbase + nt + f4i * 4);
        float4 vv = *reinterpret_cast<const float4*>(vbase + nt + f4i * 4);
        float4 w;
        w.x = expf(kv.x - mrow) * izrow;
        w.y = expf(kv.y - mrow) * izrow;
        w.z = expf(kv.z - mrow) * izrow;
        w.w = expf(kv.w - mrow) * izrow;
        *reinterpret_cast<float4*>(&ws[dl * 132 + f4i * 4]) = w;
        *reinterpret_cast<float4*>(&vs[dl * 132 + f4i * 4]) = vv;
        __syncthreads();
        #pragma unroll 8
        for (int tt = 0; tt < 32; tt++) {
            float4 wv  = *reinterpret_cast<const float4*>(&ws[d * 132 + tt * 4]);
            float4 vv2 = *reinterpret_cast<const float4*>(&vs[e * 132 + tt * 4]);
            acc += wv.x * vv2.x + wv.y * vv2.y + wv.z * vv2.z + wv.w * vv2.w;
        }
        __syncthreads();
    }
    g_ctx[((size_t)(b * HEADS_ + h) * DH_ + d) * DH_ + e] = acc * (1.f / (float)N_);
}

// ---------------------------------------------------------------------------
// K5: fused epilogue per 32-pixel tile:
//   q softmax(/sqrt d) -> attn = ctx^T q -> y = Wout@attn + bout -> LN -> +x
// grid(128, 16), 256 threads, ~49.7KB dynamic smem with phase reuse.
// smem floats: [0..4095] q | [4096..8191] ctx | [8192..12415] attn(128x33)
//              Ws reuses [0..8191]; LN red reuses [8192..]; mu/rs at [12416..]
// ---------------------------------------------------------------------------
__global__ void out_kernel(const float* __restrict__ x,
                           const float* __restrict__ bout,
                           float* __restrict__ out) {
    extern __shared__ __align__(16) float sm[];
    float* q_s   = sm;                 // 128 rows x 32 p
    float* ctx_s = sm + 4096;          // 4 x 32 x 32
    float* attn  = sm + 8192;          // 128 x 33
    float* Ws    = sm;                 // reuse: [k=32][c=256]
    float* redS  = sm + 8192;          // 32 p x 33
    float* redQ  = sm + 8192 + 1056;
    float* muS   = sm + 12416;         // 32
    float* rsS   = sm + 12448;         // 32

    const int t  = threadIdx.x;
    const int b  = blockIdx.y;
    const int n0 = blockIdx.x * 32;

    // ---- load q tile + ctx ----
    {
        int p = t & 31, r0 = t >> 5;
        const float* qb = g_qkv + (size_t)b * 384 * N_ + n0 + p;
        #pragma unroll
        for (int j = 0; j < 16; j++) {
            int r = r0 + 8 * j;
            q_s[r * 32 + p] = qb[(size_t)r * N_];
        }
        const float* cb = g_ctx + (size_t)b * (HEADS_ * DH_ * DH_);
        #pragma unroll
        for (int j = 0; j < 16; j++) ctx_s[t + 256 * j] = cb[t + 256 * j];
    }
    __syncthreads();

    // ---- q softmax over d (per head, per pixel), * 1/sqrt(32) ----
    if (t < 128) {
        int h = t >> 5, p = t & 31;
        float* col = q_s + h * 32 * 32 + p;
        float m = -1e30f;
        #pragma unroll
        for (int d = 0; d < 32; d++) m = fmaxf(m, col[d * 32]);
        float s = 0.f;
        #pragma unroll
        for (int d = 0; d < 32; d++) {
            float e = expf(col[d * 32] - m);
            col[d * 32] = e; s += e;
        }
        float sc = (1.f / s) * 0.17677669529663689f;
        #pragma unroll
        for (int d = 0; d < 32; d++) col[d * 32] *= sc;
    }
    __syncthreads();

    // ---- attn[h*32+e][p] = sum_d ctx[h][d][e] * q[h][d][p] ----
    {
        int i = t & 127, ph = t >> 7;
        int h = i >> 5, e = i & 31;
        float a[16];
        #pragma unroll
        for (int j = 0; j < 16; j++) a[j] = 0.f;
        const float* cp = ctx_s + h * 1024 + e;
        const float* qp = q_s + h * 32 * 32 + ph * 16;
        #pragma unroll
        for (int d = 0; d < 32; d++) {
            float cv = cp[d * 32];
            const float* qd = qp + d * 32;
            float4 q0 = *reinterpret_cast<const float4*>(qd);
            float4 q1 = *reinterpret_cast<const float4*>(qd + 4);
            float4 q2 = *reinterpret_cast<const float4*>(qd + 8);
            float4 q3 = *reinterpret_cast<const float4*>(qd + 12);
            a[0]  = fmaf(cv, q0.x, a[0]);  a[1]  = fmaf(cv, q0.y, a[1]);
            a[2]  = fmaf(cv, q0.z, a[2]);  a[3]  = fmaf(cv, q0.w, a[3]);
            a[4]  = fmaf(cv, q1.x, a[4]);  a[5]  = fmaf(cv, q1.y, a[5]);
            a[6]  = fmaf(cv, q1.z, a[6]);  a[7]  = fmaf(cv, q1.w, a[7]);
            a[8]  = fmaf(cv, q2.x, a[8]);  a[9]  = fmaf(cv, q2.y, a[9]);
            a[10] = fmaf(cv, q2.z, a[10]); a[11] = fmaf(cv, q2.w, a[11]);
            a[12] = fmaf(cv, q3.x, a[12]); a[13] = fmaf(cv, q3.y, a[13]);
            a[14] = fmaf(cv, q3.z, a[14]); a[15] = fmaf(cv, q3.w, a[15]);
        }
        #pragma unroll
        for (int j = 0; j < 16; j++) attn[i * 33 + ph * 16 + j] = a[j];
    }
    __syncthreads();

    // ---- y = Wout @ attn + bout (f32x2 tiled), q_s/ctx_s region reused as Ws
    const int cg = t & 31, pg = t >> 5;
    const int c0 = cg * 8, p0 = pg * 4;
    u64 acc[4][4];
    #pragma unroll
    for (int i = 0; i < 4; i++) {
        u64 bb = pack2(bout[c0 + 2 * i], bout[c0 + 2 * i + 1]);
        #pragma unroll
        for (int j = 0; j < 4; j++) acc[i][j] = bb;
    }
    for (int kc = 0; kc < 128; kc += 32) {
        #pragma unroll
        for (int k = 0; k < 32; k++)
            Ws[k * 256 + t] = g_WoutT[(kc + k) * 256 + t];
        __syncthreads();
        #pragma unroll 8
        for (int k = 0; k < 32; k++) {
            const float* ap = &attn[(kc + k) * 33 + p0];
            u64 b2[4] = { pack2(ap[0], ap[0]), pack2(ap[1], ap[1]),
                          pack2(ap[2], ap[2]), pack2(ap[3], ap[3]) };
            const ulonglong2 w01 = *reinterpret_cast<const ulonglong2*>(&Ws[k * 256 + c0]);
            const ulonglong2 w23 = *reinterpret_cast<const ulonglong2*>(&Ws[k * 256 + c0 + 4]);
            u64 w[4] = { w01.x, w01.y, w23.x, w23.y };
            #pragma unroll
            for (int i = 0; i < 4; i++)
                #pragma unroll
                for (int j = 0; j < 4; j++)
                    fma2(acc[i][j], w[i], b2[j]);
        }
        __syncthreads();
    }

    // ---- LayerNorm over channels (reduce across the 32 c-groups) ----
    {
        float ps[4] = {0.f, 0.f, 0.f, 0.f}, pq[4] = {0.f, 0.f, 0.f, 0.f};
        #pragma unroll
        for (int i = 0; i < 4; i++)
            #pragma unroll
            for (int j = 0; j < 4; j++) {
                float2 f = unpack2(acc[i][j]);
                ps[j] += f.x + f.y;
                pq[j] += f.x * f.x + f.y * f.y;
            }
        #pragma unroll
        for (int j = 0; j < 4; j++) {
            redS[(p0 + j) * 33 + cg] = ps[j];
            redQ[(p0 + j) * 33 + cg] = pq[j];
        }
    }
    __syncthreads();
    if (t < 32) {
        float S = 0.f, Q = 0.f;
        #pragma unroll
        for (int g = 0; g < 32; g++) { S += redS[t * 33 + g]; Q += redQ[t * 33 + g]; }
        float m = S * (1.f / 256.f);
        float var = Q * (1.f / 256.f) - m * m;
        muS[t] = m;
        rsS[t] = rsqrtf(var + EPS_);
    }
    __syncthreads();

    // ---- out = LN(y) + x ----
    float mus[4], rss[4];
    #pragma unroll
    for (int j = 0; j < 4; j++) { mus[j] = muS[p0 + j]; rss[j] = rsS[p0 + j]; }
    const float* xb = x + ((size_t)b * C_ + c0) * N_ + n0 + p0;
    float* ob = out + ((size_t)b * C_ + c0) * N_ + n0 + p0;
    #pragma unroll
    for (int i = 0; i < 4; i++) {
        float2 fa[4];
        #pragma unroll
        for (int j = 0; j < 4; j++) fa[j] = unpack2(acc[i][j]);
        float4 xlo = *reinterpret_cast<const float4*>(xb + (size_t)(2 * i) * N_);
        float4 xhi = *reinterpret_cast<const float4*>(xb + (size_t)(2 * i + 1) * N_);
        float4 olo = make_float4((fa[0].x - mus[0]) * rss[0] + xlo.x,
                                 (fa[1].x - mus[1]) * rss[1] + xlo.y,
                                 (fa[2].x - mus[2]) * rss[2] + xlo.z,
                                 (fa[3].x - mus[3]) * rss[3] + xlo.w);
        float4 ohi = make_float4((fa[0].y - mus[0]) * rss[0] + xhi.x,
                                 (fa[1].y - mus[1]) * rss[1] + xhi.y,
                                 (fa[2].y - mus[2]) * rss[2] + xhi.z,
                                 (fa[3].y - mus[3]) * rss[3] + xhi.w);
        *reinterpret_cast<float4*>(ob + (size_t)(2 * i) * N_)     = olo;
        *reinterpret_cast<float4*>(ob + (size_t)(2 * i + 1) * N_) = ohi;
    }
}

// ---------------------------------------------------------------------------
// launch
// ---------------------------------------------------------------------------
extern "C" void kernel_launch(void* const* d_in, const int* in_sizes, int n_in,
                              void* d_out, int out_size) {
    const float* x    = (const float*)d_in[0];
    const float* Wqkv = (const float*)d_in[1];
    const float* Wout = (const float*)d_in[2];
    const float* bout = (const float*)d_in[3];
    float* out = (float*)d_out;

    const int smemK5 = 12480 * 4;  // 49920 B > 48KB default
    cudaFuncSetAttribute(out_kernel, cudaFuncAttributeMaxDynamicSharedMemorySize, smemK5);

    transpose_kernel<<<384, 256>>>(Wqkv, Wout);
    stats_kernel<<<dim3(64, 16), 256>>>(x, g_mu, g_rstd);
    qkv_kernel<<<dim3(64, 3, 16), 256>>>(x);
    kstats_kernel<<<dim3(128, 16), 256>>>();
    ctx_kernel<<<dim3(4, 16), 1024>>>();
    out_kernel<<<dim3(128, 16), 256, smemK5>>>(x, bout, out);
}

// round 10
// speedup vs baseline: 1.0010x; 1.0010x over previous
#include <cuda_runtime.h>
#include <math.h>

// ---------------------------------------------------------------------------
// Problem constants: x[16,256,64,64], Wqkv[384,256], Wout[256,128], bout[256]
// HEADS=4, DIM_HEAD=32, N=4096
// ---------------------------------------------------------------------------
#define B_   16
#define C_   256
#define N_   4096
#define HEADS_ 4
#define DH_  32
#define INNER_ 128   // HEADS*DH
#define EPS_ 1e-5f

using u64 = unsigned long long;

// packed f32x2 helpers (Blackwell FFMA2 path)
__device__ __forceinline__ u64 pack2(float lo, float hi) {
    u64 r; asm("mov.b64 %0, {%1, %2};" : "=l"(r) : "f"(lo), "f"(hi)); return r;
}
__device__ __forceinline__ void fma2(u64 &d, u64 a, u64 b) {
    asm("fma.rn.f32x2 %0, %1, %2, %0;" : "+l"(d) : "l"(a), "l"(b));
}
__device__ __forceinline__ float2 unpack2(u64 v) {
    float2 f; asm("mov.b64 {%0, %1}, %2;" : "=f"(f.x), "=f"(f.y) : "l"(v)); return f;
}

// ---------------------------------------------------------------------------
// Scratch (device globals — no allocation allowed)
// ---------------------------------------------------------------------------
__device__ float g_qkv[B_ * 384 * N_];        // 96 MB: [b][r=0..383][n]
__device__ float g_mu[B_ * N_];
__device__ float g_rstd[B_ * N_];
__device__ float g_kmax[B_ * INNER_];         // per (b, h*32+d)
__device__ float g_kz[B_ * INNER_];
__device__ float g_ctx[B_ * HEADS_ * DH_ * DH_];   // [b][h][d][e]
__device__ float g_WqkvT[C_ * 384];           // [k][r]
__device__ float g_WoutT[INNER_ * C_];        // [k][c]

// ---------------------------------------------------------------------------
// K0: transpose weights (tiny, per-launch, deterministic)
// ---------------------------------------------------------------------------
__global__ void transpose_kernel(const float* __restrict__ Wqkv,
                                 const float* __restrict__ Wout) {
    int idx = blockIdx.x * 256 + threadIdx.x;
    if (idx < 384 * 256) {
        int r = idx / 256, k = idx % 256;
        g_WqkvT[k * 384 + r] = Wqkv[idx];
    }
    if (idx < 256 * 128) {
        int c = idx / 128, k = idx % 128;
        g_WoutT[k * 256 + c] = Wout[idx];
    }
}

// ---------------------------------------------------------------------------
// K1: per-pixel LayerNorm stats over channels (mu, rstd) — LN folded into GEMM
// grid(64, 16), 256 threads; block handles 64 consecutive pixels of batch b
// ---------------------------------------------------------------------------
__global__ void stats_kernel(const float* __restrict__ x,
                             float* __restrict__ mu, float* __restrict__ rstd) {
    __shared__ float ssum[4][64];
    __shared__ float ssq[4][64];
    int t = threadIdx.x;
    int p = t & 63, cg = t >> 6;
    int b = blockIdx.y;
    int n0 = blockIdx.x * 64;
    const float* xb = x + (size_t)b * C_ * N_ + n0 + p;
    float s = 0.f, sq = 0.f;
    #pragma unroll 8
    for (int c = cg * 64; c < cg * 64 + 64; c++) {
        float v = xb[(size_t)c * N_];
        s += v; sq += v * v;
    }
    ssum[cg][p] = s; ssq[cg][p] = sq;
    __syncthreads();
    if (t < 64) {
        float S = ssum[0][t] + ssum[1][t] + ssum[2][t] + ssum[3][t];
        float Q = ssq[0][t] + ssq[1][t] + ssq[2][t] + ssq[3][t];
        float m = S * (1.f / 256.f);
        float var = Q * (1.f / 256.f) - m * m;
        int idx = b * N_ + n0 + t;
        mu[idx] = m;
        rstd[idx] = rsqrtf(var + EPS_);
    }
}

// ---------------------------------------------------------------------------
// K2: qkv = Wqkv @ LN(x), f32x2 register-tiled GEMM.
// grid(64, 3, 16): x = 64-pixel tile, y = 128-row slab (q/k/v), z = batch.
// 256 threads: cg=t&15 -> 8 rows (4 f32x2 pairs), pg=t>>4 -> 4 pixels.
// ---------------------------------------------------------------------------
__global__ void qkv_kernel(const float* __restrict__ x) {
    __shared__ __align__(16) float Ws[32 * 132];  // [k][r pad 132]
    __shared__ __align__(16) float Bs[32 * 68];   // [k][p pad 68]

    const int t  = threadIdx.x;
    const int b  = blockIdx.z;
    const int mz = blockIdx.y;
    const int n0 = blockIdx.x * 64;
    const int m0 = mz * 128;

    const int cg = t & 15, pg = t >> 4;
    const int c0 = cg * 8, p0 = pg * 4;

    // loader coords
    const int pB = t & 63, kB = t >> 6;           // B tile: 4 k-rows, 8 passes
    const int rW = t & 127, kW0 = t >> 7;         // W tile: 2 k-rows, 16 passes
    const float mun = g_mu[b * N_ + n0 + pB];
    const float rsn = g_rstd[b * N_ + n0 + pB];

    u64 acc[4][4];
    #pragma unroll
    for (int i = 0; i < 4; i++)
        #pragma unroll
        for (int j = 0; j < 4; j++) acc[i][j] = 0ull;

    const float* xb = x + (size_t)b * C_ * N_ + n0;

    for (int kc = 0; kc < 256; kc += 32) {
        // stage B tile (normalized x) — coalesced global, conflict-free STS
        #pragma unroll
        for (int j = 0; j < 8; j++) {
            int k = kB + 4 * j;
            float v = xb[(size_t)(kc + k) * N_ + pB];
            Bs[k * 68 + pB] = (v - mun) * rsn;
        }
        // stage W tile from WqkvT (coalesced, conflict-free)
        #pragma unroll
        for (int j = 0; j < 16; j++) {
            int k = kW0 + 2 * j;
            Ws[k * 132 + rW] = g_WqkvT[(kc + k) * 384 + m0 + rW];
        }
        __syncthreads();

        #pragma unroll 8
        for (int k = 0; k < 32; k++) {
            const float4 bv = *reinterpret_cast<const float4*>(&Bs[k * 68 + p0]);
            u64 b2[4] = { pack2(bv.x, bv.x), pack2(bv.y, bv.y),
                          pack2(bv.z, bv.z), pack2(bv.w, bv.w) };
            const ulonglong2 w01 = *reinterpret_cast<const ulonglong2*>(&Ws[k * 132 + c0]);
            const ulonglong2 w23 = *reinterpret_cast<const ulonglong2*>(&Ws[k * 132 + c0 + 4]);
            u64 w[4] = { w01.x, w01.y, w23.x, w23.y };
            #pragma unroll
            for (int i = 0; i < 4; i++)
                #pragma unroll
                for (int j = 0; j < 4; j++)
                    fma2(acc[i][j], w[i], b2[j]);
        }
        __syncthreads();
    }

    float* outp = g_qkv + ((size_t)b * 384 + m0 + c0) * N_ + n0 + p0;
    #pragma unroll
    for (int i = 0; i < 4; i++) {
        float2 f0 = unpack2(acc[i][0]), f1 = unpack2(acc[i][1]);
        float2 f2 = unpack2(acc[i][2]), f3 = unpack2(acc[i][3]);
        float4 lo = make_float4(f0.x, f1.x, f2.x, f3.x);
        float4 hi = make_float4(f0.y, f1.y, f2.y, f3.y);
        *reinterpret_cast<float4*>(outp + (size_t)(2 * i) * N_)     = lo;
        *reinterpret_cast<float4*>(outp + (size_t)(2 * i + 1) * N_) = hi;
    }
}

// ---------------------------------------------------------------------------
// K3: k-softmax row stats over N for each (b, h*32+d). grid(128,16), 256 thr.
// ---------------------------------------------------------------------------
__global__ void kstats_kernel() {
    __shared__ float red[256];
    int t = threadIdx.x;
    int row = blockIdx.x;   // 0..127
    int b = blockIdx.y;
    const float* kp = g_qkv + ((size_t)b * 384 + 128 + row) * N_;
    float m = -1e30f;
    #pragma unroll 4
    for (int i = t; i < N_; i += 256) m = fmaxf(m, kp[i]);
    red[t] = m; __syncthreads();
    for (int s = 128; s > 0; s >>= 1) {
        if (t < s) red[t] = fmaxf(red[t], red[t + s]);
        __syncthreads();
    }
    m = red[0];
    __syncthreads();
    float z = 0.f;
    #pragma unroll 4
    for (int i = t; i < N_; i += 256) z += expf(kp[i] - m);
    red[t] = z; __syncthreads();
    for (int s = 128; s > 0; s >>= 1) {
        if (t < s) red[t] += red[t + s];
        __syncthreads();
    }
    if (t == 0) {
        int o = b * INNER_ + row;
        g_kmax[o] = m;
        g_kz[o] = red[0];
    }
}

// ---------------------------------------------------------------------------
// K4: ctx[b,h,d,e] = sum_n softmax_N(k)[n,d] * v[n,e] / N. grid(4,16), 1024 thr.
// ---------------------------------------------------------------------------
__global__ void ctx_kernel() {
    __shared__ __align__(16) float ws[32 * 132];
    __shared__ __align__(16) float vs[32 * 132];
    int t = threadIdx.x;
    int h = blockIdx.x, b = blockIdx.y;
    int d = t >> 5, e = t & 31;
    int dl = t >> 5, f4i = t & 31;   // loader coords
    const float* kbase = g_qkv + ((size_t)b * 384 + 128 + h * 32 + dl) * N_;
    const float* vbase = g_qkv + ((size_t)b * 384 + 256 + h * 32 + dl) * N_;
    float mrow = g_kmax[b * INNER_ + h * 32 + dl];
    float izrow = 1.f / g_kz[b * INNER_ + h * 32 + dl];
    float acc = 0.f;
    for (int nt = 0; nt < N_; nt += 128) {
        float4 kv = *reinterpret_cast<const float4*>(kbase + nt + f4i * 4);
        float4 vv = *reinterpret_cast<const float4*>(vbase + nt + f4i * 4);
        float4 w;
        w.x = expf(kv.x - mrow) * izrow;
        w.y = expf(kv.y - mrow) * izrow;
        w.z = expf(kv.z - mrow) * izrow;
        w.w = expf(kv.w - mrow) * izrow;
        *reinterpret_cast<float4*>(&ws[dl * 132 + f4i * 4]) = w;
        *reinterpret_cast<float4*>(&vs[dl * 132 + f4i * 4]) = vv;
        __syncthreads();
        #pragma unroll 8
        for (int tt = 0; tt < 32; tt++) {
            float4 wv  = *reinterpret_cast<const float4*>(&ws[d * 132 + tt * 4]);
            float4 vv2 = *reinterpret_cast<const float4*>(&vs[e * 132 + tt * 4]);
            acc += wv.x * vv2.x + wv.y * vv2.y + wv.z * vv2.z + wv.w * vv2.w;
        }
        __syncthreads();
    }
    g_ctx[((size_t)(b * HEADS_ + h) * DH_ + d) * DH_ + e] = acc * (1.f / (float)N_);
}

// ---------------------------------------------------------------------------
// K5: fused epilogue per 32-pixel tile:
//   q softmax(/sqrt d) -> attn = ctx^T q -> y = Wout@attn + bout -> LN -> +x
// grid(128, 16), 256 threads, ~49.7KB dynamic smem with phase reuse.
// smem floats: [0..4095] q | [4096..8191] ctx | [8192..12415] attn(128x33)
//              Ws reuses [0..8191]; LN red reuses [8192..]; mu/rs at [12416..]
// ---------------------------------------------------------------------------
__global__ void out_kernel(const float* __restrict__ x,
                           const float* __restrict__ bout,
                           float* __restrict__ out) {
    extern __shared__ __align__(16) float sm[];
    float* q_s   = sm;                 // 128 rows x 32 p
    float* ctx_s = sm + 4096;          // 4 x 32 x 32
    float* attn  = sm + 8192;          // 128 x 33
    float* Ws    = sm;                 // reuse: [k=32][c=256]
    float* redS  = sm + 8192;          // 32 p x 33
    float* redQ  = sm + 8192 + 1056;
    float* muS   = sm + 12416;         // 32
    float* rsS   = sm + 12448;         // 32

    const int t  = threadIdx.x;
    const int b  = blockIdx.y;
    const int n0 = blockIdx.x * 32;

    // ---- load q tile + ctx ----
    {
        int p = t & 31, r0 = t >> 5;
        const float* qb = g_qkv + (size_t)b * 384 * N_ + n0 + p;
        #pragma unroll
        for (int j = 0; j < 16; j++) {
            int r = r0 + 8 * j;
            q_s[r * 32 + p] = qb[(size_t)r * N_];
        }
        const float* cb = g_ctx + (size_t)b * (HEADS_ * DH_ * DH_);
        #pragma unroll
        for (int j = 0; j < 16; j++) ctx_s[t + 256 * j] = cb[t + 256 * j];
    }
    __syncthreads();

    // ---- q softmax over d (per head, per pixel), * 1/sqrt(32) ----
    if (t < 128) {
        int h = t >> 5, p = t & 31;
        float* col = q_s + h * 32 * 32 + p;
        float m = -1e30f;
        #pragma unroll
        for (int d = 0; d < 32; d++) m = fmaxf(m, col[d * 32]);
        float s = 0.f;
        #pragma unroll
        for (int d = 0; d < 32; d++) {
            float e = expf(col[d * 32] - m);
            col[d * 32] = e; s += e;
        }
        float sc = (1.f / s) * 0.17677669529663689f;
        #pragma unroll
        for (int d = 0; d < 32; d++) col[d * 32] *= sc;
    }
    __syncthreads();

    // ---- attn[h*32+e][p] = sum_d ctx[h][d][e] * q[h][d][p] ----
    {
        int i = t & 127, ph = t >> 7;
        int h = i >> 5, e = i & 31;
        float a[16];
        #pragma unroll
        for (int j = 0; j < 16; j++) a[j] = 0.f;
        const float* cp = ctx_s + h * 1024 + e;
        const float* qp = q_s + h * 32 * 32 + ph * 16;
        #pragma unroll
        for (int d = 0; d < 32; d++) {
            float cv = cp[d * 32];
            const float* qd = qp + d * 32;
            float4 q0 = *reinterpret_cast<const float4*>(qd);
            float4 q1 = *reinterpret_cast<const float4*>(qd + 4);
            float4 q2 = *reinterpret_cast<const float4*>(qd + 8);
            float4 q3 = *reinterpret_cast<const float4*>(qd + 12);
            a[0]  = fmaf(cv, q0.x, a[0]);  a[1]  = fmaf(cv, q0.y, a[1]);
            a[2]  = fmaf(cv, q0.z, a[2]);  a[3]  = fmaf(cv, q0.w, a[3]);
            a[4]  = fmaf(cv, q1.x, a[4]);  a[5]  = fmaf(cv, q1.y, a[5]);
            a[6]  = fmaf(cv, q1.z, a[6]);  a[7]  = fmaf(cv, q1.w, a[7]);
            a[8]  = fmaf(cv, q2.x, a[8]);  a[9]  = fmaf(cv, q2.y, a[9]);
            a[10] = fmaf(cv, q2.z, a[10]); a[11] = fmaf(cv, q2.w, a[11]);
            a[12] = fmaf(cv, q3.x, a[12]); a[13] = fmaf(cv, q3.y, a[13]);
            a[14] = fmaf(cv, q3.z, a[14]); a[15] = fmaf(cv, q3.w, a[15]);
        }
        #pragma unroll
        for (int j = 0; j < 16; j++) attn[i * 33 + ph * 16 + j] = a[j];
    }
    __syncthreads();

    // ---- y = Wout @ attn + bout (f32x2 tiled), q_s/ctx_s region reused as Ws
    const int cg = t & 31, pg = t >> 5;
    const int c0 = cg * 8, p0 = pg * 4;
    u64 acc[4][4];
    #pragma unroll
    for (int i = 0; i < 4; i++) {
        u64 bb = pack2(bout[c0 + 2 * i], bout[c0 + 2 * i + 1]);
        #pragma unroll
        for (int j = 0; j < 4; j++) acc[i][j] = bb;
    }
    for (int kc = 0; kc < 128; kc += 32) {
        #pragma unroll
        for (int k = 0; k < 32; k++)
            Ws[k * 256 + t] = g_WoutT[(kc + k) * 256 + t];
        __syncthreads();
        #pragma unroll 8
        for (int k = 0; k < 32; k++) {
            const float* ap = &attn[(kc + k) * 33 + p0];
            u64 b2[4] = { pack2(ap[0], ap[0]), pack2(ap[1], ap[1]),
                          pack2(ap[2], ap[2]), pack2(ap[3], ap[3]) };
            const ulonglong2 w01 = *reinterpret_cast<const ulonglong2*>(&Ws[k * 256 + c0]);
            const ulonglong2 w23 = *reinterpret_cast<const ulonglong2*>(&Ws[k * 256 + c0 + 4]);
            u64 w[4] = { w01.x, w01.y, w23.x, w23.y };
            #pragma unroll
            for (int i = 0; i < 4; i++)
                #pragma unroll
                for (int j = 0; j < 4; j++)
                    fma2(acc[i][j], w[i], b2[j]);
        }
        __syncthreads();
    }

    // ---- LayerNorm over channels (reduce across the 32 c-groups) ----
    {
        float ps[4] = {0.f, 0.f, 0.f, 0.f}, pq[4] = {0.f, 0.f, 0.f, 0.f};
        #pragma unroll
        for (int i = 0; i < 4; i++)
            #pragma unroll
            for (int j = 0; j < 4; j++) {
                float2 f = unpack2(acc[i][j]);
                ps[j] += f.x + f.y;
                pq[j] += f.x * f.x + f.y * f.y;
            }
        #pragma unroll
        for (int j = 0; j < 4; j++) {
            redS[(p0 + j) * 33 + cg] = ps[j];
            redQ[(p0 + j) * 33 + cg] = pq[j];
        }
    }
    __syncthreads();
    if (t < 32) {
        float S = 0.f, Q = 0.f;
        #pragma unroll
        for (int g = 0; g < 32; g++) { S += redS[t * 33 + g]; Q += redQ[t * 33 + g]; }
        float m = S * (1.f / 256.f);
        float var = Q * (1.f / 256.f) - m * m;
        muS[t] = m;
        rsS[t] = rsqrtf(var + EPS_);
    }
    __syncthreads();

    // ---- out = LN(y) + x ----
    float mus[4], rss[4];
    #pragma unroll
    for (int j = 0; j < 4; j++) { mus[j] = muS[p0 + j]; rss[j] = rsS[p0 + j]; }
    const float* xb = x + ((size_t)b * C_ + c0) * N_ + n0 + p0;
    float* ob = out + ((size_t)b * C_ + c0) * N_ + n0 + p0;
    #pragma unroll
    for (int i = 0; i < 4; i++) {
        float2 fa[4];
        #pragma unroll
        for (int j = 0; j < 4; j++) fa[j] = unpack2(acc[i][j]);
        float4 xlo = *reinterpret_cast<const float4*>(xb + (size_t)(2 * i) * N_);
        float4 xhi = *reinterpret_cast<const float4*>(xb + (size_t)(2 * i + 1) * N_);
        float4 olo = make_float4((fa[0].x - mus[0]) * rss[0] + xlo.x,
                                 (fa[1].x - mus[1]) * rss[1] + xlo.y,
                                 (fa[2].x - mus[2]) * rss[2] + xlo.z,
                                 (fa[3].x - mus[3]) * rss[3] + xlo.w);
        float4 ohi = make_float4((fa[0].y - mus[0]) * rss[0] + xhi.x,
                                 (fa[1].y - mus[1]) * rss[1] + xhi.y,
                                 (fa[2].y - mus[2]) * rss[2] + xhi.z,
                                 (fa[3].y - mus[3]) * rss[3] + xhi.w);
        *reinterpret_cast<float4*>(ob + (size_t)(2 * i) * N_)     = olo;
        *reinterpret_cast<float4*>(ob + (size_t)(2 * i + 1) * N_) = ohi;
    }
}

// ---------------------------------------------------------------------------
// launch
// ---------------------------------------------------------------------------
extern "C" void kernel_launch(void* const* d_in, const int* in_sizes, int n_in,
                              void* d_out, int out_size) {
    const float* x    = (const float*)d_in[0];
    const float* Wqkv = (const float*)d_in[1];
    const float* Wout = (const float*)d_in[2];
    const float* bout = (const float*)d_in[3];
    float* out = (float*)d_out;

    const int smemK5 = 12480 * 4;  // 49920 B > 48KB default
    cudaFuncSetAttribute(out_kernel, cudaFuncAttributeMaxDynamicSharedMemorySize, smemK5);

    transpose_kernel<<<384, 256>>>(Wqkv, Wout);
    stats_kernel<<<dim3(64, 16), 256>>>(x, g_mu, g_rstd);
    qkv_kernel<<<dim3(64, 3, 16), 256>>>(x);
    kstats_kernel<<<dim3(128, 16), 256>>>();
    ctx_kernel<<<dim3(4, 16), 1024>>>();
    out_kernel<<<dim3(128, 16), 256, smemK5>>>(x, bout, out);
}

// round 11
// speedup vs baseline: 1.0017x; 1.0006x over previous
#include <cuda_runtime.h>
#include <math.h>

// ---------------------------------------------------------------------------
// Problem constants: x[16,256,64,64], Wqkv[384,256], Wout[256,128], bout[256]
// HEADS=4, DIM_HEAD=32, N=4096
// ---------------------------------------------------------------------------
#define B_   16
#define C_   256
#define N_   4096
#define HEADS_ 4
#define DH_  32
#define INNER_ 128   // HEADS*DH
#define EPS_ 1e-5f

using u64 = unsigned long long;

// packed f32x2 helpers (Blackwell FFMA2 path)
__device__ __forceinline__ u64 pack2(float lo, float hi) {
    u64 r; asm("mov.b64 %0, {%1, %2};" : "=l"(r) : "f"(lo), "f"(hi)); return r;
}
__device__ __forceinline__ void fma2(u64 &d, u64 a, u64 b) {
    asm("fma.rn.f32x2 %0, %1, %2, %0;" : "+l"(d) : "l"(a), "l"(b));
}
__device__ __forceinline__ float2 unpack2(u64 v) {
    float2 f; asm("mov.b64 {%0, %1}, %2;" : "=f"(f.x), "=f"(f.y) : "l"(v)); return f;
}

// ---------------------------------------------------------------------------
// Scratch (device globals — no allocation allowed)
// ---------------------------------------------------------------------------
__device__ float g_qkv[B_ * 384 * N_];        // 96 MB: [b][r=0..383][n]
__device__ float g_mu[B_ * N_];
__device__ float g_rstd[B_ * N_];
__device__ float g_kmax[B_ * INNER_];         // per (b, h*32+d)
__device__ float g_kz[B_ * INNER_];
__device__ float g_ctx[B_ * HEADS_ * DH_ * DH_];   // [b][h][d][e]
__device__ float g_WqkvT[C_ * 384];           // [k][r]
__device__ float g_WoutT[INNER_ * C_];        // [k][c]

// ---------------------------------------------------------------------------
// K0: transpose weights (tiny, per-launch, deterministic)
// ---------------------------------------------------------------------------
__global__ void transpose_kernel(const float* __restrict__ Wqkv,
                                 const float* __restrict__ Wout) {
    int idx = blockIdx.x * 256 + threadIdx.x;
    if (idx < 384 * 256) {
        int r = idx / 256, k = idx % 256;
        g_WqkvT[k * 384 + r] = Wqkv[idx];
    }
    if (idx < 256 * 128) {
        int c = idx / 128, k = idx % 128;
        g_WoutT[k * 256 + c] = Wout[idx];
    }
}

// ---------------------------------------------------------------------------
// K1: per-pixel LayerNorm stats over channels (mu, rstd) — LN folded into GEMM
// grid(64, 16), 256 threads; block handles 64 consecutive pixels of batch b
// ---------------------------------------------------------------------------
__global__ void stats_kernel(const float* __restrict__ x,
                             float* __restrict__ mu, float* __restrict__ rstd) {
    __shared__ float ssum[4][64];
    __shared__ float ssq[4][64];
    int t = threadIdx.x;
    int p = t & 63, cg = t >> 6;
    int b = blockIdx.y;
    int n0 = blockIdx.x * 64;
    const float* xb = x + (size_t)b * C_ * N_ + n0 + p;
    float s = 0.f, sq = 0.f;
    #pragma unroll 8
    for (int c = cg * 64; c < cg * 64 + 64; c++) {
        float v = xb[(size_t)c * N_];
        s += v; sq += v * v;
    }
    ssum[cg][p] = s; ssq[cg][p] = sq;
    __syncthreads();
    if (t < 64) {
        float S = ssum[0][t] + ssum[1][t] + ssum[2][t] + ssum[3][t];
        float Q = ssq[0][t] + ssq[1][t] + ssq[2][t] + ssq[3][t];
        float m = S * (1.f / 256.f);
        float var = Q * (1.f / 256.f) - m * m;
        int idx = b * N_ + n0 + t;
        mu[idx] = m;
        rstd[idx] = rsqrtf(var + EPS_);
    }
}

// ---------------------------------------------------------------------------
// K2: qkv = Wqkv @ LN(x), f32x2 register-tiled GEMM.
// grid(64, 3, 16): x = 64-pixel tile, y = 128-row slab (q/k/v), z = batch.
// 256 threads: cg=t&15 -> 8 rows (4 f32x2 pairs), pg=t>>4 -> 4 pixels.
// ---------------------------------------------------------------------------
__global__ void qkv_kernel(const float* __restrict__ x) {
    __shared__ __align__(16) float Ws[32 * 132];  // [k][r pad 132]
    __shared__ __align__(16) float Bs[32 * 68];   // [k][p pad 68]

    const int t  = threadIdx.x;
    const int b  = blockIdx.z;
    const int mz = blockIdx.y;
    const int n0 = blockIdx.x * 64;
    const int m0 = mz * 128;

    const int cg = t & 15, pg = t >> 4;
    const int c0 = cg * 8, p0 = pg * 4;

    // loader coords
    const int pB = t & 63, kB = t >> 6;           // B tile: 4 k-rows, 8 passes
    const int rW = t & 127, kW0 = t >> 7;         // W tile: 2 k-rows, 16 passes
    const float mun = g_mu[b * N_ + n0 + pB];
    const float rsn = g_rstd[b * N_ + n0 + pB];

    u64 acc[4][4];
    #pragma unroll
    for (int i = 0; i < 4; i++)
        #pragma unroll
        for (int j = 0; j < 4; j++) acc[i][j] = 0ull;

    const float* xb = x + (size_t)b * C_ * N_ + n0;

    for (int kc = 0; kc < 256; kc += 32) {
        // stage B tile (normalized x) — coalesced global, conflict-free STS
        #pragma unroll
        for (int j = 0; j < 8; j++) {
            int k = kB + 4 * j;
            float v = xb[(size_t)(kc + k) * N_ + pB];
            Bs[k * 68 + pB] = (v - mun) * rsn;
        }
        // stage W tile from WqkvT (coalesced, conflict-free)
        #pragma unroll
        for (int j = 0; j < 16; j++) {
            int k = kW0 + 2 * j;
            Ws[k * 132 + rW] = g_WqkvT[(kc + k) * 384 + m0 + rW];
        }
        __syncthreads();

        #pragma unroll 8
        for (int k = 0; k < 32; k++) {
            const float4 bv = *reinterpret_cast<const float4*>(&Bs[k * 68 + p0]);
            u64 b2[4] = { pack2(bv.x, bv.x), pack2(bv.y, bv.y),
                          pack2(bv.z, bv.z), pack2(bv.w, bv.w) };
            const ulonglong2 w01 = *reinterpret_cast<const ulonglong2*>(&Ws[k * 132 + c0]);
            const ulonglong2 w23 = *reinterpret_cast<const ulonglong2*>(&Ws[k * 132 + c0 + 4]);
            u64 w[4] = { w01.x, w01.y, w23.x, w23.y };
            #pragma unroll
            for (int i = 0; i < 4; i++)
                #pragma unroll
                for (int j = 0; j < 4; j++)
                    fma2(acc[i][j], w[i], b2[j]);
        }
        __syncthreads();
    }

    float* outp = g_qkv + ((size_t)b * 384 + m0 + c0) * N_ + n0 + p0;
    #pragma unroll
    for (int i = 0; i < 4; i++) {
        float2 f0 = unpack2(acc[i][0]), f1 = unpack2(acc[i][1]);
        float2 f2 = unpack2(acc[i][2]), f3 = unpack2(acc[i][3]);
        float4 lo = make_float4(f0.x, f1.x, f2.x, f3.x);
        float4 hi = make_float4(f0.y, f1.y, f2.y, f3.y);
        *reinterpret_cast<float4*>(outp + (size_t)(2 * i) * N_)     = lo;
        *reinterpret_cast<float4*>(outp + (size_t)(2 * i + 1) * N_) = hi;
    }
}

// ---------------------------------------------------------------------------
// K3: k-softmax row stats over N for each (b, h*32+d). grid(128,16), 256 thr.
// ---------------------------------------------------------------------------
__global__ void kstats_kernel() {
    __shared__ float red[256];
    int t = threadIdx.x;
    int row = blockIdx.x;   // 0..127
    int b = blockIdx.y;
    const float* kp = g_qkv + ((size_t)b * 384 + 128 + row) * N_;
    float m = -1e30f;
    #pragma unroll 4
    for (int i = t; i < N_; i += 256) m = fmaxf(m, kp[i]);
    red[t] = m; __syncthreads();
    for (int s = 128; s > 0; s >>= 1) {
        if (t < s) red[t] = fmaxf(red[t], red[t + s]);
        __syncthreads();
    }
    m = red[0];
    __syncthreads();
    float z = 0.f;
    #pragma unroll 4
    for (int i = t; i < N_; i += 256) z += expf(kp[i] - m);
    red[t] = z; __syncthreads();
    for (int s = 128; s > 0; s >>= 1) {
        if (t < s) red[t] += red[t + s];
        __syncthreads();
    }
    if (t == 0) {
        int o = b * INNER_ + row;
        g_kmax[o] = m;
        g_kz[o] = red[0];
    }
}

// ---------------------------------------------------------------------------
// K4: ctx[b,h,d,e] = sum_n softmax_N(k)[n,d] * v[n,e] / N. grid(4,16), 1024 thr.
// ---------------------------------------------------------------------------
__global__ void ctx_kernel() {
    __shared__ __align__(16) float ws[32 * 132];
    __shared__ __align__(16) float vs[32 * 132];
    int t = threadIdx.x;
    int h = blockIdx.x, b = blockIdx.y;
    int d = t >> 5, e = t & 31;
    int dl = t >> 5, f4i = t & 31;   // loader coords
    const float* kbase = g_qkv + ((size_t)b * 384 + 128 + h * 32 + dl) * N_;
    const float* vbase = g_qkv + ((size_t)b * 384 + 256 + h * 32 + dl) * N_;
    float mrow = g_kmax[b * INNER_ + h * 32 + dl];
    float izrow = 1.f / g_kz[b * INNER_ + h * 32 + dl];
    float acc = 0.f;
    for (int nt = 0; nt < N_; nt += 128) {
        float4 kv = *reinterpret_cast<const float4*>(kbase + nt + f4i * 4);
        float4 vv = *reinterpret_cast<const float4*>(vbase + nt + f4i * 4);
        float4 w;
        w.x = expf(kv.x - mrow) * izrow;
        w.y = expf(kv.y - mrow) * izrow;
        w.z = expf(kv.z - mrow) * izrow;
        w.w = expf(kv.w - mrow) * izrow;
        *reinterpret_cast<float4*>(&ws[dl * 132 + f4i * 4]) = w;
        *reinterpret_cast<float4*>(&vs[dl * 132 + f4i * 4]) = vv;
        __syncthreads();
        #pragma unroll 8
        for (int tt = 0; tt < 32; tt++) {
            float4 wv  = *reinterpret_cast<const float4*>(&ws[d * 132 + tt * 4]);
            float4 vv2 = *reinterpret_cast<const float4*>(&vs[e * 132 + tt * 4]);
            acc += wv.x * vv2.x + wv.y * vv2.y + wv.z * vv2.z + wv.w * vv2.w;
        }
        __syncthreads();
    }
    g_ctx[((size_t)(b * HEADS_ + h) * DH_ + d) * DH_ + e] = acc * (1.f / (float)N_);
}

// ---------------------------------------------------------------------------
// K5: fused epilogue per 32-pixel tile:
//   q softmax(/sqrt d) -> attn = ctx^T q -> y = Wout@attn + bout -> LN -> +x
// grid(128, 16), 256 threads, ~49.7KB dynamic smem with phase reuse.
// smem floats: [0..4095] q | [4096..8191] ctx | [8192..12415] attn(128x33)
//              Ws reuses [0..8191]; LN red reuses [8192..]; mu/rs at [12416..]
// ---------------------------------------------------------------------------
__global__ void out_kernel(const float* __restrict__ x,
                           const float* __restrict__ bout,
                           float* __restrict__ out) {
    extern __shared__ __align__(16) float sm[];
    float* q_s   = sm;                 // 128 rows x 32 p
    float* ctx_s = sm + 4096;          // 4 x 32 x 32
    float* attn  = sm + 8192;          // 128 x 33
    float* Ws    = sm;                 // reuse: [k=32][c=256]
    float* redS  = sm + 8192;          // 32 p x 33
    float* redQ  = sm + 8192 + 1056;
    float* muS   = sm + 12416;         // 32
    float* rsS   = sm + 12448;         // 32

    const int t  = threadIdx.x;
    const int b  = blockIdx.y;
    const int n0 = blockIdx.x * 32;

    // ---- load q tile + ctx ----
    {
        int p = t & 31, r0 = t >> 5;
        const float* qb = g_qkv + (size_t)b * 384 * N_ + n0 + p;
        #pragma unroll
        for (int j = 0; j < 16; j++) {
            int r = r0 + 8 * j;
            q_s[r * 32 + p] = qb[(size_t)r * N_];
        }
        const float* cb = g_ctx + (size_t)b * (HEADS_ * DH_ * DH_);
        #pragma unroll
        for (int j = 0; j < 16; j++) ctx_s[t + 256 * j] = cb[t + 256 * j];
    }
    __syncthreads();

    // ---- q softmax over d (per head, per pixel), * 1/sqrt(32) ----
    if (t < 128) {
        int h = t >> 5, p = t & 31;
        float* col = q_s + h * 32 * 32 + p;
        float m = -1e30f;
        #pragma unroll
        for (int d = 0; d < 32; d++) m = fmaxf(m, col[d * 32]);
        float s = 0.f;
        #pragma unroll
        for (int d = 0; d < 32; d++) {
            float e = expf(col[d * 32] - m);
            col[d * 32] = e; s += e;
        }
        float sc = (1.f / s) * 0.17677669529663689f;
        #pragma unroll
        for (int d = 0; d < 32; d++) col[d * 32] *= sc;
    }
    __syncthreads();

    // ---- attn[h*32+e][p] = sum_d ctx[h][d][e] * q[h][d][p] ----
    {
        int i = t & 127, ph = t >> 7;
        int h = i >> 5, e = i & 31;
        float a[16];
        #pragma unroll
        for (int j = 0; j < 16; j++) a[j] = 0.f;
        const float* cp = ctx_s + h * 1024 + e;
        const float* qp = q_s + h * 32 * 32 + ph * 16;
        #pragma unroll
        for (int d = 0; d < 32; d++) {
            float cv = cp[d * 32];
            const float* qd = qp + d * 32;
            float4 q0 = *reinterpret_cast<const float4*>(qd);
            float4 q1 = *reinterpret_cast<const float4*>(qd + 4);
            float4 q2 = *reinterpret_cast<const float4*>(qd + 8);
            float4 q3 = *reinterpret_cast<const float4*>(qd + 12);
            a[0]  = fmaf(cv, q0.x, a[0]);  a[1]  = fmaf(cv, q0.y, a[1]);
            a[2]  = fmaf(cv, q0.z, a[2]);  a[3]  = fmaf(cv, q0.w, a[3]);
            a[4]  = fmaf(cv, q1.x, a[4]);  a[5]  = fmaf(cv, q1.y, a[5]);
            a[6]  = fmaf(cv, q1.z, a[6]);  a[7]  = fmaf(cv, q1.w, a[7]);
            a[8]  = fmaf(cv, q2.x, a[8]);  a[9]  = fmaf(cv, q2.y, a[9]);
            a[10] = fmaf(cv, q2.z, a[10]); a[11] = fmaf(cv, q2.w, a[11]);
            a[12] = fmaf(cv, q3.x, a[12]); a[13] = fmaf(cv, q3.y, a[13]);
            a[14] = fmaf(cv, q3.z, a[14]); a[15] = fmaf(cv, q3.w, a[15]);
        }
        #pragma unroll
        for (int j = 0; j < 16; j++) attn[i * 33 + ph * 16 + j] = a[j];
    }
    __syncthreads();

    // ---- y = Wout @ attn + bout (f32x2 tiled), q_s/ctx_s region reused as Ws
    const int cg = t & 31, pg = t >> 5;
    const int c0 = cg * 8, p0 = pg * 4;
    u64 acc[4][4];
    #pragma unroll
    for (int i = 0; i < 4; i++) {
        u64 bb = pack2(bout[c0 + 2 * i], bout[c0 + 2 * i + 1]);
        #pragma unroll
        for (int j = 0; j < 4; j++) acc[i][j] = bb;
    }
    for (int kc = 0; kc < 128; kc += 32) {
        #pragma unroll
        for (int k = 0; k < 32; k++)
            Ws[k * 256 + t] = g_WoutT[(kc + k) * 256 + t];
        __syncthreads();
        #pragma unroll 8
        for (int k = 0; k < 32; k++) {
            const float* ap = &attn[(kc + k) * 33 + p0];
            u64 b2[4] = { pack2(ap[0], ap[0]), pack2(ap[1], ap[1]),
                          pack2(ap[2], ap[2]), pack2(ap[3], ap[3]) };
            const ulonglong2 w01 = *reinterpret_cast<const ulonglong2*>(&Ws[k * 256 + c0]);
            const ulonglong2 w23 = *reinterpret_cast<const ulonglong2*>(&Ws[k * 256 + c0 + 4]);
            u64 w[4] = { w01.x, w01.y, w23.x, w23.y };
            #pragma unroll
            for (int i = 0; i < 4; i++)
                #pragma unroll
                for (int j = 0; j < 4; j++)
                    fma2(acc[i][j], w[i], b2[j]);
        }
        __syncthreads();
    }

    // ---- LayerNorm over channels (reduce across the 32 c-groups) ----
    {
        float ps[4] = {0.f, 0.f, 0.f, 0.f}, pq[4] = {0.f, 0.f, 0.f, 0.f};
        #pragma unroll
        for (int i = 0; i < 4; i++)
            #pragma unroll
            for (int j = 0; j < 4; j++) {
                float2 f = unpack2(acc[i][j]);
                ps[j] += f.x + f.y;
                pq[j] += f.x * f.x + f.y * f.y;
            }
        #pragma unroll
        for (int j = 0; j < 4; j++) {
            redS[(p0 + j) * 33 + cg] = ps[j];
            redQ[(p0 + j) * 33 + cg] = pq[j];
        }
    }
    __syncthreads();
    if (t < 32) {
        float S = 0.f, Q = 0.f;
        #pragma unroll
        for (int g = 0; g < 32; g++) { S += redS[t * 33 + g]; Q += redQ[t * 33 + g]; }
        float m = S * (1.f / 256.f);
        float var = Q * (1.f / 256.f) - m * m;
        muS[t] = m;
        rsS[t] = rsqrtf(var + EPS_);
    }
    __syncthreads();

    // ---- out = LN(y) + x ----
    float mus[4], rss[4];
    #pragma unroll
    for (int j = 0; j < 4; j++) { mus[j] = muS[p0 + j]; rss[j] = rsS[p0 + j]; }
    const float* xb = x + ((size_t)b * C_ + c0) * N_ + n0 + p0;
    float* ob = out + ((size_t)b * C_ + c0) * N_ + n0 + p0;
    #pragma unroll
    for (int i = 0; i < 4; i++) {
        float2 fa[4];
        #pragma unroll
        for (int j = 0; j < 4; j++) fa[j] = unpack2(acc[i][j]);
        float4 xlo = *reinterpret_cast<const float4*>(xb + (size_t)(2 * i) * N_);
        float4 xhi = *reinterpret_cast<const float4*>(xb + (size_t)(2 * i + 1) * N_);
        float4 olo = make_float4((fa[0].x - mus[0]) * rss[0] + xlo.x,
                                 (fa[1].x - mus[1]) * rss[1] + xlo.y,
                                 (fa[2].x - mus[2]) * rss[2] + xlo.z,
                                 (fa[3].x - mus[3]) * rss[3] + xlo.w);
        float4 ohi = make_float4((fa[0].y - mus[0]) * rss[0] + xhi.x,
                                 (fa[1].y - mus[1]) * rss[1] + xhi.y,
                                 (fa[2].y - mus[2]) * rss[2] + xhi.z,
                                 (fa[3].y - mus[3]) * rss[3] + xhi.w);
        *reinterpret_cast<float4*>(ob + (size_t)(2 * i) * N_)     = olo;
        *reinterpret_cast<float4*>(ob + (size_t)(2 * i + 1) * N_) = ohi;
    }
}

// ---------------------------------------------------------------------------
// launch
// ---------------------------------------------------------------------------
extern "C" void kernel_launch(void* const* d_in, const int* in_sizes, int n_in,
                              void* d_out, int out_size) {
    const float* x    = (const float*)d_in[0];
    const float* Wqkv = (const float*)d_in[1];
    const float* Wout = (const float*)d_in[2];
    const float* bout = (const float*)d_in[3];
    float* out = (float*)d_out;

    const int smemK5 = 12480 * 4;  // 49920 B > 48KB default
    cudaFuncSetAttribute(out_kernel, cudaFuncAttributeMaxDynamicSharedMemorySize, smemK5);

    transpose_kernel<<<384, 256>>>(Wqkv, Wout);
    stats_kernel<<<dim3(64, 16), 256>>>(x, g_mu, g_rstd);
    qkv_kernel<<<dim3(64, 3, 16), 256>>>(x);
    kstats_kernel<<<dim3(128, 16), 256>>>();
    ctx_kernel<<<dim3(4, 16), 1024>>>();
    out_kernel<<<dim3(128, 16), 256, smemK5>>>(x, bout, out);
}

// round 12
// speedup vs baseline: 1.0023x; 1.0006x over previous
#include <cuda_runtime.h>
#include <math.h>

// ---------------------------------------------------------------------------
// Problem constants: x[16,256,64,64], Wqkv[384,256], Wout[256,128], bout[256]
// HEADS=4, DIM_HEAD=32, N=4096
// ---------------------------------------------------------------------------
#define B_   16
#define C_   256
#define N_   4096
#define HEADS_ 4
#define DH_  32
#define INNER_ 128   // HEADS*DH
#define EPS_ 1e-5f

using u64 = unsigned long long;

// packed f32x2 helpers (Blackwell FFMA2 path)
__device__ __forceinline__ u64 pack2(float lo, float hi) {
    u64 r; asm("mov.b64 %0, {%1, %2};" : "=l"(r) : "f"(lo), "f"(hi)); return r;
}
__device__ __forceinline__ void fma2(u64 &d, u64 a, u64 b) {
    asm("fma.rn.f32x2 %0, %1, %2, %0;" : "+l"(d) : "l"(a), "l"(b));
}
__device__ __forceinline__ float2 unpack2(u64 v) {
    float2 f; asm("mov.b64 {%0, %1}, %2;" : "=f"(f.x), "=f"(f.y) : "l"(v)); return f;
}

// ---------------------------------------------------------------------------
// Scratch (device globals — no allocation allowed)
// ---------------------------------------------------------------------------
__device__ float g_qkv[B_ * 384 * N_];        // 96 MB: [b][r=0..383][n]
__device__ float g_mu[B_ * N_];
__device__ float g_rstd[B_ * N_];
__device__ float g_kmax[B_ * INNER_];         // per (b, h*32+d)
__device__ float g_kz[B_ * INNER_];
__device__ float g_ctx[B_ * HEADS_ * DH_ * DH_];   // [b][h][d][e]
__device__ float g_WqkvT[C_ * 384];           // [k][r]
__device__ float g_WoutT[INNER_ * C_];        // [k][c]

// ---------------------------------------------------------------------------
// K0: transpose weights (tiny, per-launch, deterministic)
// ---------------------------------------------------------------------------
__global__ void transpose_kernel(const float* __restrict__ Wqkv,
                                 const float* __restrict__ Wout) {
    int idx = blockIdx.x * 256 + threadIdx.x;
    if (idx < 384 * 256) {
        int r = idx / 256, k = idx % 256;
        g_WqkvT[k * 384 + r] = Wqkv[idx];
    }
    if (idx < 256 * 128) {
        int c = idx / 128, k = idx % 128;
        g_WoutT[k * 256 + c] = Wout[idx];
    }
}

// ---------------------------------------------------------------------------
// K1: per-pixel LayerNorm stats over channels (mu, rstd) — LN folded into GEMM
// grid(64, 16), 256 threads; block handles 64 consecutive pixels of batch b
// ---------------------------------------------------------------------------
__global__ void stats_kernel(const float* __restrict__ x,
                             float* __restrict__ mu, float* __restrict__ rstd) {
    __shared__ float ssum[4][64];
    __shared__ float ssq[4][64];
    int t = threadIdx.x;
    int p = t & 63, cg = t >> 6;
    int b = blockIdx.y;
    int n0 = blockIdx.x * 64;
    const float* xb = x + (size_t)b * C_ * N_ + n0 + p;
    float s = 0.f, sq = 0.f;
    #pragma unroll 8
    for (int c = cg * 64; c < cg * 64 + 64; c++) {
        float v = xb[(size_t)c * N_];
        s += v; sq += v * v;
    }
    ssum[cg][p] = s; ssq[cg][p] = sq;
    __syncthreads();
    if (t < 64) {
        float S = ssum[0][t] + ssum[1][t] + ssum[2][t] + ssum[3][t];
        float Q = ssq[0][t] + ssq[1][t] + ssq[2][t] + ssq[3][t];
        float m = S * (1.f / 256.f);
        float var = Q * (1.f / 256.f) - m * m;
        int idx = b * N_ + n0 + t;
        mu[idx] = m;
        rstd[idx] = rsqrtf(var + EPS_);
    }
}

// ---------------------------------------------------------------------------
// K2: qkv = Wqkv @ LN(x), f32x2 register-tiled GEMM.
// grid(64, 3, 16): x = 64-pixel tile, y = 128-row slab (q/k/v), z = batch.
// 256 threads: cg=t&15 -> 8 rows (4 f32x2 pairs), pg=t>>4 -> 4 pixels.
// ---------------------------------------------------------------------------
__global__ void qkv_kernel(const float* __restrict__ x) {
    __shared__ __align__(16) float Ws[32 * 132];  // [k][r pad 132]
    __shared__ __align__(16) float Bs[32 * 68];   // [k][p pad 68]

    const int t  = threadIdx.x;
    const int b  = blockIdx.z;
    const int mz = blockIdx.y;
    const int n0 = blockIdx.x * 64;
    const int m0 = mz * 128;

    const int cg = t & 15, pg = t >> 4;
    const int c0 = cg * 8, p0 = pg * 4;

    // loader coords
    const int pB = t & 63, kB = t >> 6;           // B tile: 4 k-rows, 8 passes
    const int rW = t & 127, kW0 = t >> 7;         // W tile: 2 k-rows, 16 passes
    const float mun = g_mu[b * N_ + n0 + pB];
    const float rsn = g_rstd[b * N_ + n0 + pB];

    u64 acc[4][4];
    #pragma unroll
    for (int i = 0; i < 4; i++)
        #pragma unroll
        for (int j = 0; j < 4; j++) acc[i][j] = 0ull;

    const float* xb = x + (size_t)b * C_ * N_ + n0;

    for (int kc = 0; kc < 256; kc += 32) {
        // stage B tile (normalized x) — coalesced global, conflict-free STS
        #pragma unroll
        for (int j = 0; j < 8; j++) {
            int k = kB + 4 * j;
            float v = xb[(size_t)(kc + k) * N_ + pB];
            Bs[k * 68 + pB] = (v - mun) * rsn;
        }
        // stage W tile from WqkvT (coalesced, conflict-free)
        #pragma unroll
        for (int j = 0; j < 16; j++) {
            int k = kW0 + 2 * j;
            Ws[k * 132 + rW] = g_WqkvT[(kc + k) * 384 + m0 + rW];
        }
        __syncthreads();

        #pragma unroll 8
        for (int k = 0; k < 32; k++) {
            const float4 bv = *reinterpret_cast<const float4*>(&Bs[k * 68 + p0]);
            u64 b2[4] = { pack2(bv.x, bv.x), pack2(bv.y, bv.y),
                          pack2(bv.z, bv.z), pack2(bv.w, bv.w) };
            const ulonglong2 w01 = *reinterpret_cast<const ulonglong2*>(&Ws[k * 132 + c0]);
            const ulonglong2 w23 = *reinterpret_cast<const ulonglong2*>(&Ws[k * 132 + c0 + 4]);
            u64 w[4] = { w01.x, w01.y, w23.x, w23.y };
            #pragma unroll
            for (int i = 0; i < 4; i++)
                #pragma unroll
                for (int j = 0; j < 4; j++)
                    fma2(acc[i][j], w[i], b2[j]);
        }
        __syncthreads();
    }

    float* outp = g_qkv + ((size_t)b * 384 + m0 + c0) * N_ + n0 + p0;
    #pragma unroll
    for (int i = 0; i < 4; i++) {
        float2 f0 = unpack2(acc[i][0]), f1 = unpack2(acc[i][1]);
        float2 f2 = unpack2(acc[i][2]), f3 = unpack2(acc[i][3]);
        float4 lo = make_float4(f0.x, f1.x, f2.x, f3.x);
        float4 hi = make_float4(f0.y, f1.y, f2.y, f3.y);
        *reinterpret_cast<float4*>(outp + (size_t)(2 * i) * N_)     = lo;
        *reinterpret_cast<float4*>(outp + (size_t)(2 * i + 1) * N_) = hi;
    }
}

// ---------------------------------------------------------------------------
// K3: k-softmax row stats over N for each (b, h*32+d). grid(128,16), 256 thr.
// ---------------------------------------------------------------------------
__global__ void kstats_kernel() {
    __shared__ float red[256];
    int t = threadIdx.x;
    int row = blockIdx.x;   // 0..127
    int b = blockIdx.y;
    const float* kp = g_qkv + ((size_t)b * 384 + 128 + row) * N_;
    float m = -1e30f;
    #pragma unroll 4
    for (int i = t; i < N_; i += 256) m = fmaxf(m, kp[i]);
    red[t] = m; __syncthreads();
    for (int s = 128; s > 0; s >>= 1) {
        if (t < s) red[t] = fmaxf(red[t], red[t + s]);
        __syncthreads();
    }
    m = red[0];
    __syncthreads();
    float z = 0.f;
    #pragma unroll 4
    for (int i = t; i < N_; i += 256) z += expf(kp[i] - m);
    red[t] = z; __syncthreads();
    for (int s = 128; s > 0; s >>= 1) {
        if (t < s) red[t] += red[t + s];
        __syncthreads();
    }
    if (t == 0) {
        int o = b * INNER_ + row;
        g_kmax[o] = m;
        g_kz[o] = red[0];
    }
}

// ---------------------------------------------------------------------------
// K4: ctx[b,h,d,e] = sum_n softmax_N(k)[n,d] * v[n,e] / N. grid(4,16), 1024 thr.
// ---------------------------------------------------------------------------
__global__ void ctx_kernel() {
    __shared__ __align__(16) float ws[32 * 132];
    __shared__ __align__(16) float vs[32 * 132];
    int t = threadIdx.x;
    int h = blockIdx.x, b = blockIdx.y;
    int d = t >> 5, e = t & 31;
    int dl = t >> 5, f4i = t & 31;   // loader coords
    const float* kbase = g_qkv + ((size_t)b * 384 + 128 + h * 32 + dl) * N_;
    const float* vbase = g_qkv + ((size_t)b * 384 + 256 + h * 32 + dl) * N_;
    float mrow = g_kmax[b * INNER_ + h * 32 + dl];
    float izrow = 1.f / g_kz[b * INNER_ + h * 32 + dl];
    float acc = 0.f;
    for (int nt = 0; nt < N_; nt += 128) {
        float4 kv = *reinterpret_cast<const float4*>(kbase + nt + f4i * 4);
        float4 vv = *reinterpret_cast<const float4*>(vbase + nt + f4i * 4);
        float4 w;
        w.x = expf(kv.x - mrow) * izrow;
        w.y = expf(kv.y - mrow) * izrow;
        w.z = expf(kv.z - mrow) * izrow;
        w.w = expf(kv.w - mrow) * izrow;
        *reinterpret_cast<float4*>(&ws[dl * 132 + f4i * 4]) = w;
        *reinterpret_cast<float4*>(&vs[dl * 132 + f4i * 4]) = vv;
        __syncthreads();
        #pragma unroll 8
        for (int tt = 0; tt < 32; tt++) {
            float4 wv  = *reinterpret_cast<const float4*>(&ws[d * 132 + tt * 4]);
            float4 vv2 = *reinterpret_cast<const float4*>(&vs[e * 132 + tt * 4]);
            acc += wv.x * vv2.x + wv.y * vv2.y + wv.z * vv2.z + wv.w * vv2.w;
        }
        __syncthreads();
    }
    g_ctx[((size_t)(b * HEADS_ + h) * DH_ + d) * DH_ + e] = acc * (1.f / (float)N_);
}

// ---------------------------------------------------------------------------
// K5: fused epilogue per 32-pixel tile:
//   q softmax(/sqrt d) -> attn = ctx^T q -> y = Wout@attn + bout -> LN -> +x
// grid(128, 16), 256 threads, ~49.7KB dynamic smem with phase reuse.
// smem floats: [0..4095] q | [4096..8191] ctx | [8192..12415] attn(128x33)
//              Ws reuses [0..8191]; LN red reuses [8192..]; mu/rs at [12416..]
// ---------------------------------------------------------------------------
__global__ void out_kernel(const float* __restrict__ x,
                           const float* __restrict__ bout,
                           float* __restrict__ out) {
    extern __shared__ __align__(16) float sm[];
    float* q_s   = sm;                 // 128 rows x 32 p
    float* ctx_s = sm + 4096;          // 4 x 32 x 32
    float* attn  = sm + 8192;          // 128 x 33
    float* Ws    = sm;                 // reuse: [k=32][c=256]
    float* redS  = sm + 8192;          // 32 p x 33
    float* redQ  = sm + 8192 + 1056;
    float* muS   = sm + 12416;         // 32
    float* rsS   = sm + 12448;         // 32

    const int t  = threadIdx.x;
    const int b  = blockIdx.y;
    const int n0 = blockIdx.x * 32;

    // ---- load q tile + ctx ----
    {
        int p = t & 31, r0 = t >> 5;
        const float* qb = g_qkv + (size_t)b * 384 * N_ + n0 + p;
        #pragma unroll
        for (int j = 0; j < 16; j++) {
            int r = r0 + 8 * j;
            q_s[r * 32 + p] = qb[(size_t)r * N_];
        }
        const float* cb = g_ctx + (size_t)b * (HEADS_ * DH_ * DH_);
        #pragma unroll
        for (int j = 0; j < 16; j++) ctx_s[t + 256 * j] = cb[t + 256 * j];
    }
    __syncthreads();

    // ---- q softmax over d (per head, per pixel), * 1/sqrt(32) ----
    if (t < 128) {
        int h = t >> 5, p = t & 31;
        float* col = q_s + h * 32 * 32 + p;
        float m = -1e30f;
        #pragma unroll
        for (int d = 0; d < 32; d++) m = fmaxf(m, col[d * 32]);
        float s = 0.f;
        #pragma unroll
        for (int d = 0; d < 32; d++) {
            float e = expf(col[d * 32] - m);
            col[d * 32] = e; s += e;
        }
        float sc = (1.f / s) * 0.17677669529663689f;
        #pragma unroll
        for (int d = 0; d < 32; d++) col[d * 32] *= sc;
    }
    __syncthreads();

    // ---- attn[h*32+e][p] = sum_d ctx[h][d][e] * q[h][d][p] ----
    {
        int i = t & 127, ph = t >> 7;
        int h = i >> 5, e = i & 31;
        float a[16];
        #pragma unroll
        for (int j = 0; j < 16; j++) a[j] = 0.f;
        const float* cp = ctx_s + h * 1024 + e;
        const float* qp = q_s + h * 32 * 32 + ph * 16;
        #pragma unroll
        for (int d = 0; d < 32; d++) {
            float cv = cp[d * 32];
            const float* qd = qp + d * 32;
            float4 q0 = *reinterpret_cast<const float4*>(qd);
            float4 q1 = *reinterpret_cast<const float4*>(qd + 4);
            float4 q2 = *reinterpret_cast<const float4*>(qd + 8);
            float4 q3 = *reinterpret_cast<const float4*>(qd + 12);
            a[0]  = fmaf(cv, q0.x, a[0]);  a[1]  = fmaf(cv, q0.y, a[1]);
            a[2]  = fmaf(cv, q0.z, a[2]);  a[3]  = fmaf(cv, q0.w, a[3]);
            a[4]  = fmaf(cv, q1.x, a[4]);  a[5]  = fmaf(cv, q1.y, a[5]);
            a[6]  = fmaf(cv, q1.z, a[6]);  a[7]  = fmaf(cv, q1.w, a[7]);
            a[8]  = fmaf(cv, q2.x, a[8]);  a[9]  = fmaf(cv, q2.y, a[9]);
            a[10] = fmaf(cv, q2.z, a[10]); a[11] = fmaf(cv, q2.w, a[11]);
            a[12] = fmaf(cv, q3.x, a[12]); a[13] = fmaf(cv, q3.y, a[13]);
            a[14] = fmaf(cv, q3.z, a[14]); a[15] = fmaf(cv, q3.w, a[15]);
        }
        #pragma unroll
        for (int j = 0; j < 16; j++) attn[i * 33 + ph * 16 + j] = a[j];
    }
    __syncthreads();

    // ---- y = Wout @ attn + bout (f32x2 tiled), q_s/ctx_s region reused as Ws
    const int cg = t & 31, pg = t >> 5;
    const int c0 = cg * 8, p0 = pg * 4;
    u64 acc[4][4];
    #pragma unroll
    for (int i = 0; i < 4; i++) {
        u64 bb = pack2(bout[c0 + 2 * i], bout[c0 + 2 * i + 1]);
        #pragma unroll
        for (int j = 0; j < 4; j++) acc[i][j] = bb;
    }
    for (int kc = 0; kc < 128; kc += 32) {
        #pragma unroll
        for (int k = 0; k < 32; k++)
            Ws[k * 256 + t] = g_WoutT[(kc + k) * 256 + t];
        __syncthreads();
        #pragma unroll 8
        for (int k = 0; k < 32; k++) {
            const float* ap = &attn[(kc + k) * 33 + p0];
            u64 b2[4] = { pack2(ap[0], ap[0]), pack2(ap[1], ap[1]),
                          pack2(ap[2], ap[2]), pack2(ap[3], ap[3]) };
            const ulonglong2 w01 = *reinterpret_cast<const ulonglong2*>(&Ws[k * 256 + c0]);
            const ulonglong2 w23 = *reinterpret_cast<const ulonglong2*>(&Ws[k * 256 + c0 + 4]);
            u64 w[4] = { w01.x, w01.y, w23.x, w23.y };
            #pragma unroll
            for (int i = 0; i < 4; i++)
                #pragma unroll
                for (int j = 0; j < 4; j++)
                    fma2(acc[i][j], w[i], b2[j]);
        }
        __syncthreads();
    }

    // ---- LayerNorm over channels (reduce across the 32 c-groups) ----
    {
        float ps[4] = {0.f, 0.f, 0.f, 0.f}, pq[4] = {0.f, 0.f, 0.f, 0.f};
        #pragma unroll
        for (int i = 0; i < 4; i++)
            #pragma unroll
            for (int j = 0; j < 4; j++) {
                float2 f = unpack2(acc[i][j]);
                ps[j] += f.x + f.y;
                pq[j] += f.x * f.x + f.y * f.y;
            }
        #pragma unroll
        for (int j = 0; j < 4; j++) {
            redS[(p0 + j) * 33 + cg] = ps[j];
            redQ[(p0 + j) * 33 + cg] = pq[j];
        }
    }
    __syncthreads();
    if (t < 32) {
        float S = 0.f, Q = 0.f;
        #pragma unroll
        for (int g = 0; g < 32; g++) { S += redS[t * 33 + g]; Q += redQ[t * 33 + g]; }
        float m = S * (1.f / 256.f);
        float var = Q * (1.f / 256.f) - m * m;
        muS[t] = m;
        rsS[t] = rsqrtf(var + EPS_);
    }
    __syncthreads();

    // ---- out = LN(y) + x ----
    float mus[4], rss[4];
    #pragma unroll
    for (int j = 0; j < 4; j++) { mus[j] = muS[p0 + j]; rss[j] = rsS[p0 + j]; }
    const float* xb = x + ((size_t)b * C_ + c0) * N_ + n0 + p0;
    float* ob = out + ((size_t)b * C_ + c0) * N_ + n0 + p0;
    #pragma unroll
    for (int i = 0; i < 4; i++) {
        float2 fa[4];
        #pragma unroll
        for (int j = 0; j < 4; j++) fa[j] = unpack2(acc[i][j]);
        float4 xlo = *reinterpret_cast<const float4*>(xb + (size_t)(2 * i) * N_);
        float4 xhi = *reinterpret_cast<const float4*>(xb + (size_t)(2 * i + 1) * N_);
        float4 olo = make_float4((fa[0].x - mus[0]) * rss[0] + xlo.x,
                                 (fa[1].x - mus[1]) * rss[1] + xlo.y,
                                 (fa[2].x - mus[2]) * rss[2] + xlo.z,
                                 (fa[3].x - mus[3]) * rss[3] + xlo.w);
        float4 ohi = make_float4((fa[0].y - mus[0]) * rss[0] + xhi.x,
                                 (fa[1].y - mus[1]) * rss[1] + xhi.y,
                                 (fa[2].y - mus[2]) * rss[2] + xhi.z,
                                 (fa[3].y - mus[3]) * rss[3] + xhi.w);
        *reinterpret_cast<float4*>(ob + (size_t)(2 * i) * N_)     = olo;
        *reinterpret_cast<float4*>(ob + (size_t)(2 * i + 1) * N_) = ohi;
    }
}

// ---------------------------------------------------------------------------
// launch
// ---------------------------------------------------------------------------
extern "C" void kernel_launch(void* const* d_in, const int* in_sizes, int n_in,
                              void* d_out, int out_size) {
    const float* x    = (const float*)d_in[0];
    const float* Wqkv = (const float*)d_in[1];
    const float* Wout = (const float*)d_in[2];
    const float* bout = (const float*)d_in[3];
    float* out = (float*)d_out;

    const int smemK5 = 12480 * 4;  // 49920 B > 48KB default
    cudaFuncSetAttribute(out_kernel, cudaFuncAttributeMaxDynamicSharedMemorySize, smemK5);

    transpose_kernel<<<384, 256>>>(Wqkv, Wout);
    stats_kernel<<<dim3(64, 16), 256>>>(x, g_mu, g_rstd);
    qkv_kernel<<<dim3(64, 3, 16), 256>>>(x);
    kstats_kernel<<<dim3(128, 16), 256>>>();
    ctx_kernel<<<dim3(4, 16), 1024>>>();
    out_kernel<<<dim3(128, 16), 256, smemK5>>>(x, bout, out);
}

// round 13
// speedup vs baseline: 2.2192x; 2.2141x over previous
#include <cuda_runtime.h>
#include <math.h>
#include <stdint.h>

// ---------------------------------------------------------------------------
// Problem: x[16,256,64,64], Wqkv[384,256], Wout[256,128], bout[256]
// HEADS=4, DIM_HEAD=32, N=4096
// ---------------------------------------------------------------------------
#define B_    16
#define C_    256
#define N_    4096
#define HEADS_ 4
#define DH_   32
#define INNER_ 128
#define EPS_  1e-5f

// ---------------------------------------------------------------------------
// Scratch (device globals — no allocation allowed)
// ---------------------------------------------------------------------------
__device__ float g_qkv[B_ * 384 * N_];              // [b][r=0..383][n]
__device__ float g_mu[B_ * N_];
__device__ float g_rstd[B_ * N_];
__device__ float g_kmax[B_ * INNER_];
__device__ float g_kz[B_ * INNER_];
__device__ float g_ctxp[4 * B_ * HEADS_ * DH_ * DH_];   // [nc][b][h][d][e]

// ---------------------------------------------------------------------------
// tf32 helpers
// ---------------------------------------------------------------------------
__device__ __forceinline__ uint32_t f2tf(float f) {
    uint32_t r; asm("cvt.rna.tf32.f32 %0, %1;" : "=r"(r) : "f"(f)); return r;
}

#define MMA_TF32(D, a0, a1, a2, a3, b0, b1)                                  \
    asm volatile(                                                            \
        "mma.sync.aligned.m16n8k8.row.col.f32.tf32.tf32.f32 "                \
        "{%0,%1,%2,%3}, {%4,%5,%6,%7}, {%8,%9}, {%0,%1,%2,%3};"              \
        : "+f"((D)[0]), "+f"((D)[1]), "+f"((D)[2]), "+f"((D)[3])             \
        : "r"(a0), "r"(a1), "r"(a2), "r"(a3), "r"(b0), "r"(b1))

// ---------------------------------------------------------------------------
// K1: per-pixel LayerNorm stats over channels (mu, rstd)
// grid(64, 16), 256 threads
// ---------------------------------------------------------------------------
__global__ void stats_kernel(const float* __restrict__ x) {
    __shared__ float ssum[4][64];
    __shared__ float ssq[4][64];
    int t = threadIdx.x;
    int p = t & 63, cg = t >> 6;
    int b = blockIdx.y;
    int n0 = blockIdx.x * 64;
    const float* xb = x + (size_t)b * C_ * N_ + n0 + p;
    float s = 0.f, sq = 0.f;
    #pragma unroll 8
    for (int c = cg * 64; c < cg * 64 + 64; c++) {
        float v = xb[(size_t)c * N_];
        s += v; sq += v * v;
    }
    ssum[cg][p] = s; ssq[cg][p] = sq;
    __syncthreads();
    if (t < 64) {
        float S = ssum[0][t] + ssum[1][t] + ssum[2][t] + ssum[3][t];
        float Q = ssq[0][t] + ssq[1][t] + ssq[2][t] + ssq[3][t];
        float m = S * (1.f / 256.f);
        float var = Q * (1.f / 256.f) - m * m;
        int idx = b * N_ + n0 + t;
        g_mu[idx] = m;
        g_rstd[idx] = rsqrtf(var + EPS_);
    }
}

// ---------------------------------------------------------------------------
// K2: qkv = Wqkv @ LN(x)  — tf32 tensor-core GEMM
// grid(64 px-tiles of 64, 3 m-slabs of 128, 16 b), 256 threads (8 warps 4x2)
// As[128][36] (pad 36: conflict-free A frags), Bs[32][72] (pad 72: B frags)
// ---------------------------------------------------------------------------
__global__ void qkv_kernel(const float* __restrict__ x,
                           const float* __restrict__ Wqkv) {
    __shared__ uint32_t As[128 * 36];   // 18432 B
    __shared__ uint32_t Bs[32 * 72];    //  9216 B

    const int t = threadIdx.x;
    const int lane = t & 31, w = t >> 5;
    const int b = blockIdx.z;
    const int m0 = blockIdx.y * 128;
    const int n0 = blockIdx.x * 64;
    const int m0w = (w & 3) * 32, n0w = (w >> 2) * 32;

    // staging coords
    const int mA = t >> 1, hA = t & 1;         // A: row mA, k-half hA
    const int kB = t >> 3, ngB = t & 7;        // B: k-row kB, 8 pixels ngB*8..

    float mun[8], rsn[8];
    {
        const float* mp = g_mu + b * N_ + n0 + ngB * 8;
        const float* rp = g_rstd + b * N_ + n0 + ngB * 8;
        #pragma unroll
        for (int j = 0; j < 8; j++) { mun[j] = mp[j]; rsn[j] = rp[j]; }
    }

    float d[2][4][4];
    #pragma unroll
    for (int i = 0; i < 2; i++)
        #pragma unroll
        for (int j = 0; j < 4; j++)
            #pragma unroll
            for (int k = 0; k < 4; k++) d[i][j][k] = 0.f;

    const float* xb = x + (size_t)b * C_ * N_ + n0;

    for (int kc = 0; kc < 256; kc += 32) {
        // ---- stage A (Wqkv rows m0..m0+127, cols kc..kc+31) ----
        {
            const float* ga = Wqkv + (size_t)(m0 + mA) * 256 + kc + hA * 16;
            uint32_t* as = As + mA * 36 + hA * 16;
            #pragma unroll
            for (int i = 0; i < 4; i++) {
                float4 v = *reinterpret_cast<const float4*>(ga + 4 * i);
                as[4 * i + 0] = f2tf(v.x); as[4 * i + 1] = f2tf(v.y);
                as[4 * i + 2] = f2tf(v.z); as[4 * i + 3] = f2tf(v.w);
            }
        }
        // ---- stage B (LN-normalized x, rows kc..kc+31, cols n0..n0+63) ----
        {
            const float* gb = xb + (size_t)(kc + kB) * N_ + ngB * 8;
            uint32_t* bs = Bs + kB * 72 + ngB * 8;
            #pragma unroll
            for (int i = 0; i < 2; i++) {
                float4 v = *reinterpret_cast<const float4*>(gb + 4 * i);
                bs[4 * i + 0] = f2tf((v.x - mun[4 * i + 0]) * rsn[4 * i + 0]);
                bs[4 * i + 1] = f2tf((v.y - mun[4 * i + 1]) * rsn[4 * i + 1]);
                bs[4 * i + 2] = f2tf((v.z - mun[4 * i + 2]) * rsn[4 * i + 2]);
                bs[4 * i + 3] = f2tf((v.w - mun[4 * i + 3]) * rsn[4 * i + 3]);
            }
        }
        __syncthreads();

        #pragma unroll
        for (int kk = 0; kk < 32; kk += 8) {
            const uint32_t* Ap = As + (m0w + (lane >> 2)) * 36 + kk + (lane & 3);
            uint32_t a00 = Ap[0],       a01 = Ap[8 * 36],
                     a02 = Ap[4],       a03 = Ap[8 * 36 + 4];
            uint32_t a10 = Ap[16 * 36], a11 = Ap[24 * 36],
                     a12 = Ap[16 * 36 + 4], a13 = Ap[24 * 36 + 4];
            const uint32_t* Bp = Bs + (kk + (lane & 3)) * 72 + n0w + (lane >> 2);
            #pragma unroll
            for (int nt = 0; nt < 4; nt++) {
                uint32_t b0 = Bp[nt * 8], b1 = Bp[4 * 72 + nt * 8];
                MMA_TF32(d[0][nt], a00, a01, a02, a03, b0, b1);
                MMA_TF32(d[1][nt], a10, a11, a12, a13, b0, b1);
            }
        }
        __syncthreads();
    }

    // ---- write: c0 (r, 2c), c1 (r, 2c+1), c2 (r+8, 2c), c3 (r+8, 2c+1) ----
    #pragma unroll
    for (int mt = 0; mt < 2; mt++) {
        int r = m0 + m0w + mt * 16 + (lane >> 2);
        float* orow = g_qkv + ((size_t)b * 384 + r) * N_ + n0 + n0w + 2 * (lane & 3);
        #pragma unroll
        for (int nt = 0; nt < 4; nt++) {
            *reinterpret_cast<float2*>(orow + nt * 8) =
                make_float2(d[mt][nt][0], d[mt][nt][1]);
            *reinterpret_cast<float2*>(orow + nt * 8 + 8 * N_) =
                make_float2(d[mt][nt][2], d[mt][nt][3]);
        }
    }
}

// ---------------------------------------------------------------------------
// K3: k-softmax row stats over N per (b, h*32+d). grid(128,16), 256 thr.
// ---------------------------------------------------------------------------
__global__ void kstats_kernel() {
    __shared__ float red[256];
    int t = threadIdx.x;
    int row = blockIdx.x;
    int b = blockIdx.y;
    const float* kp = g_qkv + ((size_t)b * 384 + 128 + row) * N_;
    float m = -1e30f;
    #pragma unroll 4
    for (int i = t; i < N_; i += 256) m = fmaxf(m, kp[i]);
    red[t] = m; __syncthreads();
    for (int s = 128; s > 0; s >>= 1) {
        if (t < s) red[t] = fmaxf(red[t], red[t + s]);
        __syncthreads();
    }
    m = red[0];
    __syncthreads();
    float z = 0.f;
    #pragma unroll 4
    for (int i = t; i < N_; i += 256) z += expf(kp[i] - m);
    red[t] = z; __syncthreads();
    for (int s = 128; s > 0; s >>= 1) {
        if (t < s) red[t] += red[t + s];
        __syncthreads();
    }
    if (t == 0) {
        int o = b * INNER_ + row;
        g_kmax[o] = m;
        g_kz[o] = red[0];
    }
}

// ---------------------------------------------------------------------------
// K4: ctx[d][e] = sum_n softmaxN(k)[d][n] * v[e][n]  — tf32 MMA over K=n
// grid(4 h, 16 b, 4 n-chunks), 128 threads (4 warps; warps split k8 steps).
// A = exp-weights ws[d][132] (natural), B = v vs[e][132] read as col-major.
// Partials into g_ctxp; out_kernel sums the 4 chunks. 1/N folded here.
// ---------------------------------------------------------------------------
__global__ void ctx_kernel() {
    __shared__ uint32_t sbuf[2 * 32 * 132];   // ws | vs ; red aliases
    uint32_t* ws = sbuf;
    uint32_t* vs = sbuf + 32 * 132;

    const int t = threadIdx.x;
    const int lane = t & 31, w = t >> 5;
    const int h = blockIdx.x, b = blockIdx.y, nc = blockIdx.z;
    const int r = t >> 2, seg = t & 3;

    const float* kbase = g_qkv + ((size_t)(b * 384 + 128 + h * 32 + r)) * N_
                         + nc * 1024 + seg * 32;
    const float* vbase = g_qkv + ((size_t)(b * 384 + 256 + h * 32 + r)) * N_
                         + nc * 1024 + seg * 32;
    const float mrow = g_kmax[b * INNER_ + h * 32 + r];
    const float izrow = 1.f / g_kz[b * INNER_ + h * 32 + r];

    float d[2][4][4];
    #pragma unroll
    for (int i = 0; i < 2; i++)
        #pragma unroll
        for (int j = 0; j < 4; j++)
            #pragma unroll
            for (int k = 0; k < 4; k++) d[i][j][k] = 0.f;

    for (int n0c = 0; n0c < 1024; n0c += 128) {
        uint32_t* wp = ws + r * 132 + seg * 32;
        uint32_t* vp = vs + r * 132 + seg * 32;
        #pragma unroll
        for (int j = 0; j < 8; j++) {
            float4 kv = *reinterpret_cast<const float4*>(kbase + n0c + 4 * j);
            wp[4 * j + 0] = f2tf(expf(kv.x - mrow) * izrow);
            wp[4 * j + 1] = f2tf(expf(kv.y - mrow) * izrow);
            wp[4 * j + 2] = f2tf(expf(kv.z - mrow) * izrow);
            wp[4 * j + 3] = f2tf(expf(kv.w - mrow) * izrow);
            float4 vv = *reinterpret_cast<const float4*>(vbase + n0c + 4 * j);
            vp[4 * j + 0] = f2tf(vv.x);
            vp[4 * j + 1] = f2tf(vv.y);
            vp[4 * j + 2] = f2tf(vv.z);
            vp[4 * j + 3] = f2tf(vv.w);
        }
        __syncthreads();

        #pragma unroll
        for (int s = 0; s < 4; s++) {
            const int kk = s * 32 + w * 8;
            const uint32_t* Ap = ws + (lane >> 2) * 132 + kk + (lane & 3);
            uint32_t a00 = Ap[0],        a01 = Ap[8 * 132],
                     a02 = Ap[4],        a03 = Ap[8 * 132 + 4];
            uint32_t a10 = Ap[16 * 132], a11 = Ap[24 * 132],
                     a12 = Ap[16 * 132 + 4], a13 = Ap[24 * 132 + 4];
            const uint32_t* Bp = vs + (lane >> 2) * 132 + kk + (lane & 3);
            #pragma unroll
            for (int nt = 0; nt < 4; nt++) {
                uint32_t b0 = Bp[nt * 8 * 132], b1 = Bp[nt * 8 * 132 + 4];
                MMA_TF32(d[0][nt], a00, a01, a02, a03, b0, b1);
                MMA_TF32(d[1][nt], a10, a11, a12, a13, b0, b1);
            }
        }
        __syncthreads();
    }

    // cross-warp reduce through smem (red[4][32][34], pad 34 for float2 align)
    float* red = reinterpret_cast<float*>(sbuf);
    #pragma unroll
    for (int mt = 0; mt < 2; mt++) {
        int dd = mt * 16 + (lane >> 2);
        #pragma unroll
        for (int nt = 0; nt < 4; nt++) {
            int e = nt * 8 + 2 * (lane & 3);
            *reinterpret_cast<float2*>(&red[w * 1088 + dd * 34 + e]) =
                make_float2(d[mt][nt][0], d[mt][nt][1]);
            *reinterpret_cast<float2*>(&red[w * 1088 + (dd + 8) * 34 + e]) =
                make_float2(d[mt][nt][2], d[mt][nt][3]);
        }
    }
    __syncthreads();
    {
        const int dd = t >> 2, e0 = (t & 3) * 8;
        float* outp = g_ctxp + ((size_t)((nc * 16 + b) * 4 + h)) * 1024 + dd * 32 + e0;
        #pragma unroll
        for (int j = 0; j < 8; j++) {
            float s = red[0 * 1088 + dd * 34 + e0 + j]
                    + red[1 * 1088 + dd * 34 + e0 + j]
                    + red[2 * 1088 + dd * 34 + e0 + j]
                    + red[3 * 1088 + dd * 34 + e0 + j];
            outp[j] = s * (1.f / (float)N_);
        }
    }
}

// ---------------------------------------------------------------------------
// K5: fused epilogue per 32-pixel tile: q softmax -> attn = ctx^T q ->
//     y = Wout@attn + bout (tf32 MMA) -> LN -> +x
// grid(128, 16), 256 threads, 57600 B dynamic smem, phase-aliased regions.
// Region A [0..9216): q_s(4096)+ctx_s(4096) -> As[256][36] -> ySm[256][34]
// Region B [9216..14336): attn[128][40] -> redS/redQ
// Tail [14336..14400): muS(32), rsS(32)
// ---------------------------------------------------------------------------
__global__ void out_kernel(const float* __restrict__ x,
                           const float* __restrict__ Wout,
                           const float* __restrict__ bout,
                           float* __restrict__ out) {
    extern __shared__ __align__(16) float sm[];
    float*    q_s   = sm;
    float*    ctx_s = sm + 4096;
    uint32_t* As    = reinterpret_cast<uint32_t*>(sm);
    float*    ySm   = sm;
    float*    attnF = sm + 9216;
    uint32_t* attnU = reinterpret_cast<uint32_t*>(attnF);
    float*    redS  = attnF;
    float*    redQ  = attnF + 256;
    float*    muS   = sm + 14336;
    float*    rsS   = sm + 14368;

    const int t = threadIdx.x;
    const int lane = t & 31, w = t >> 5;
    const int b = blockIdx.y;
    const int n0 = blockIdx.x * 32;

    // ---- phase 1: load q tile + summed ctx partials ----
    {
        int p = t & 31, r0 = t >> 5;
        const float* qb = g_qkv + (size_t)b * 384 * N_ + n0 + p;
        #pragma unroll
        for (int j = 0; j < 16; j++) {
            int r = r0 + 8 * j;
            q_s[r * 32 + p] = qb[(size_t)r * N_];
        }
        #pragma unroll
        for (int j = 0; j < 16; j++) {
            int i = t + 256 * j;
            int hh = i >> 10, off = i & 1023;
            float s = 0.f;
            #pragma unroll
            for (int pp = 0; pp < 4; pp++)
                s += g_ctxp[((size_t)((pp * 16 + b) * 4 + hh)) * 1024 + off];
            ctx_s[i] = s;
        }
    }
    __syncthreads();

    // ---- phase 2: q softmax over d (per head, per pixel), * 1/sqrt(32) ----
    if (t < 128) {
        int h = t >> 5, p = t & 31;
        float* col = q_s + h * 1024 + p;
        float m = -1e30f;
        #pragma unroll
        for (int dd = 0; dd < 32; dd++) m = fmaxf(m, col[dd * 32]);
        float s = 0.f;
        #pragma unroll
        for (int dd = 0; dd < 32; dd++) {
            float e = expf(col[dd * 32] - m);
            col[dd * 32] = e; s += e;
        }
        float sc = (1.f / s) * 0.17677669529663689f;
        #pragma unroll
        for (int dd = 0; dd < 32; dd++) col[dd * 32] *= sc;
    }
    __syncthreads();

    // ---- phase 3: attn[h*32+e][p] = sum_d ctx[h][d][e] * q[h][d][p] ----
    {
        int i = t & 127, ph = t >> 7;
        int h = i >> 5, e = i & 31;
        float a[16];
        #pragma unroll
        for (int j = 0; j < 16; j++) a[j] = 0.f;
        const float* cp = ctx_s + h * 1024 + e;
        const float* qp = q_s + h * 1024 + ph * 16;
        #pragma unroll
        for (int dd = 0; dd < 32; dd++) {
            float cv = cp[dd * 32];
            const float* qd = qp + dd * 32;
            float4 q0 = *reinterpret_cast<const float4*>(qd);
            float4 q1 = *reinterpret_cast<const float4*>(qd + 4);
            float4 q2 = *reinterpret_cast<const float4*>(qd + 8);
            float4 q3 = *reinterpret_cast<const float4*>(qd + 12);
            a[0]  = fmaf(cv, q0.x, a[0]);  a[1]  = fmaf(cv, q0.y, a[1]);
            a[2]  = fmaf(cv, q0.z, a[2]);  a[3]  = fmaf(cv, q0.w, a[3]);
            a[4]  = fmaf(cv, q1.x, a[4]);  a[5]  = fmaf(cv, q1.y, a[5]);
            a[6]  = fmaf(cv, q1.z, a[6]);  a[7]  = fmaf(cv, q1.w, a[7]);
            a[8]  = fmaf(cv, q2.x, a[8]);  a[9]  = fmaf(cv, q2.y, a[9]);
            a[10] = fmaf(cv, q2.z, a[10]); a[11] = fmaf(cv, q2.w, a[11]);
            a[12] = fmaf(cv, q3.x, a[12]); a[13] = fmaf(cv, q3.y, a[13]);
            a[14] = fmaf(cv, q3.z, a[14]); a[15] = fmaf(cv, q3.w, a[15]);
        }
        #pragma unroll
        for (int j = 0; j < 16; j++) attnU[i * 40 + ph * 16 + j] = f2tf(a[j]);
    }
    __syncthreads();

    // ---- phase 4: y = Wout @ attn (tf32 MMA; warp w owns rows w*32..+31) --
    float dacc[2][4][4];
    #pragma unroll
    for (int i = 0; i < 2; i++)
        #pragma unroll
        for (int j = 0; j < 4; j++)
            #pragma unroll
            for (int k = 0; k < 4; k++) dacc[i][j][k] = 0.f;

    for (int kc = 0; kc < 128; kc += 32) {
        // stage A: thread t loads Wout row t, cols kc..kc+31
        {
            const float* gw = Wout + (size_t)t * 128 + kc;
            uint32_t* as = As + t * 36;
            #pragma unroll
            for (int i = 0; i < 8; i++) {
                float4 v = *reinterpret_cast<const float4*>(gw + 4 * i);
                as[4 * i + 0] = f2tf(v.x); as[4 * i + 1] = f2tf(v.y);
                as[4 * i + 2] = f2tf(v.z); as[4 * i + 3] = f2tf(v.w);
            }
        }
        __syncthreads();
        #pragma unroll
        for (int kk = 0; kk < 32; kk += 8) {
            const uint32_t* Ap = As + (w * 32 + (lane >> 2)) * 36 + kk + (lane & 3);
            uint32_t a00 = Ap[0],       a01 = Ap[8 * 36],
                     a02 = Ap[4],       a03 = Ap[8 * 36 + 4];
            uint32_t a10 = Ap[16 * 36], a11 = Ap[24 * 36],
                     a12 = Ap[16 * 36 + 4], a13 = Ap[24 * 36 + 4];
            const uint32_t* Bp = attnU + (kc + kk + (lane & 3)) * 40 + (lane >> 2);
            #pragma unroll
            for (int nt = 0; nt < 4; nt++) {
                uint32_t b0 = Bp[nt * 8], b1 = Bp[4 * 40 + nt * 8];
                MMA_TF32(dacc[0][nt], a00, a01, a02, a03, b0, b1);
                MMA_TF32(dacc[1][nt], a10, a11, a12, a13, b0, b1);
            }
        }
        __syncthreads();
    }

    // ---- phase 5: add bias, store y into ySm[256][34] ----
    {
        float bb[2][2];
        bb[0][0] = bout[w * 32 + (lane >> 2)];
        bb[0][1] = bout[w * 32 + 8 + (lane >> 2)];
        bb[1][0] = bout[w * 32 + 16 + (lane >> 2)];
        bb[1][1] = bout[w * 32 + 24 + (lane >> 2)];
        #pragma unroll
        for (int mt = 0; mt < 2; mt++) {
            int ch = w * 32 + mt * 16 + (lane >> 2);
            #pragma unroll
            for (int nt = 0; nt < 4; nt++) {
                int px = nt * 8 + 2 * (lane & 3);
                *reinterpret_cast<float2*>(&ySm[ch * 34 + px]) =
                    make_float2(dacc[mt][nt][0] + bb[mt][0],
                                dacc[mt][nt][1] + bb[mt][0]);
                *reinterpret_cast<float2*>(&ySm[(ch + 8) * 34 + px]) =
                    make_float2(dacc[mt][nt][2] + bb[mt][1],
                                dacc[mt][nt][3] + bb[mt][1]);
            }
        }
    }
    __syncthreads();

    // ---- phase 6: LN stats over 256 channels per pixel ----
    {
        int grp = t >> 5, px = t & 31;
        float S = 0.f, Q = 0.f;
        #pragma unroll
        for (int i = 0; i < 32; i++) {
            float v = ySm[(grp * 32 + i) * 34 + px];
            S += v; Q += v * v;
        }
        redS[grp * 32 + px] = S;
        redQ[grp * 32 + px] = Q;
    }
    __syncthreads();
    if (t < 32) {
        float S = 0.f, Q = 0.f;
        #pragma unroll
        for (int g = 0; g < 8; g++) { S += redS[g * 32 + t]; Q += redQ[g * 32 + t]; }
        float m = S * (1.f / 256.f);
        float var = Q * (1.f / 256.f) - m * m;
        muS[t] = m;
        rsS[t] = rsqrtf(var + EPS_);
    }
    __syncthreads();

    // ---- phase 7: out = LN(y) + x (coalesced along n) ----
    {
        int grp = t >> 5, px = t & 31;
        float mu = muS[px], rs = rsS[px];
        const float* xb = x + ((size_t)b * C_ + grp * 32) * N_ + n0 + px;
        float* ob = out + ((size_t)b * C_ + grp * 32) * N_ + n0 + px;
        #pragma unroll
        for (int i = 0; i < 32; i++) {
            float v = (ySm[(grp * 32 + i) * 34 + px] - mu) * rs + xb[(size_t)i * N_];
            ob[(size_t)i * N_] = v;
        }
    }
}

// ---------------------------------------------------------------------------
// launch
// ---------------------------------------------------------------------------
extern "C" void kernel_launch(void* const* d_in, const int* in_sizes, int n_in,
                              void* d_out, int out_size) {
    const float* x    = (const float*)d_in[0];
    const float* Wqkv = (const float*)d_in[1];
    const float* Wout = (const float*)d_in[2];
    const float* bout = (const float*)d_in[3];
    float* out = (float*)d_out;

    const int smemK5 = 14400 * 4;  // 57600 B
    cudaFuncSetAttribute(out_kernel, cudaFuncAttributeMaxDynamicSharedMemorySize, smemK5);

    stats_kernel<<<dim3(64, 16), 256>>>(x);
    qkv_kernel<<<dim3(64, 3, 16), 256>>>(x, Wqkv);
    kstats_kernel<<<dim3(128, 16), 256>>>();
    ctx_kernel<<<dim3(4, 16, 4), 128>>>();
    out_kernel<<<dim3(128, 16), 256, smemK5>>>(x, Wout, bout, out);
}